// round 1
// baseline (speedup 1.0000x reference)
#include <cuda_runtime.h>
#include <math.h>

#define L_TOK 32768

// ---------------- scratch (device globals; no runtime allocation) ----------------
__device__ float g_x  [L_TOK * 256];   // residual stream
__device__ float g_win[L_TOK * 256];   // LN output / partitioned windows
__device__ float g_qkv[L_TOK * 768];   // qkv
__device__ float g_att[L_TOK * 256];   // attention out (window layout)
__device__ float g_mlp[L_TOK * 1024];  // MLP hidden

// window-layout row r -> original token index (handles cyclic shift roll)
__device__ __forceinline__ int win_to_tok(int r, int shift) {
    int w = r >> 6, n = r & 63;
    int h  = ((w >> 6) << 2)        + (n >> 4);
    int wy = (((w >> 3) & 7) << 2)  + ((n >> 2) & 3);
    int t  = ((w & 7) << 2)         + (n & 3);
    h  = (h  + shift) & 31;
    wy = (wy + shift) & 31;
    t  = (t  + shift) & 31;
    return (h << 10) + (wy << 5) + t;
}

// ---------------- residual init ----------------
__global__ void k_copy(const float* __restrict__ src) {
    int i = blockIdx.x * 256 + threadIdx.x;
    ((float4*)g_x)[i] = ((const float4*)src)[i];
}

// ---------------- LayerNorm (REMAP=1: fused shift+partition gather) ----------------
template<int REMAP>
__global__ __launch_bounds__(256) void k_ln(const float* __restrict__ gam,
                                            const float* __restrict__ bet, int shift) {
    int warp = threadIdx.x >> 5, lane = threadIdx.x & 31;
    int r = (blockIdx.x << 3) + warp;
    int src = REMAP ? win_to_tok(r, shift) : r;
    const float4* xp = (const float4*)(g_x + src * 256);
    float4 a = xp[lane * 2], c = xp[lane * 2 + 1];
    float s  = a.x + a.y + a.z + a.w + c.x + c.y + c.z + c.w;
    float sq = a.x*a.x + a.y*a.y + a.z*a.z + a.w*a.w
             + c.x*c.x + c.y*c.y + c.z*c.z + c.w*c.w;
    #pragma unroll
    for (int o = 16; o; o >>= 1) {
        s  += __shfl_xor_sync(0xffffffffu, s, o);
        sq += __shfl_xor_sync(0xffffffffu, sq, o);
    }
    float mean = s * (1.0f / 256.0f);
    float inv = rsqrtf(sq * (1.0f / 256.0f) - mean * mean + 1e-5f);
    float4 g0 = ((const float4*)gam)[lane*2], g1 = ((const float4*)gam)[lane*2+1];
    float4 b0 = ((const float4*)bet)[lane*2], b1 = ((const float4*)bet)[lane*2+1];
    float4 o0, o1;
    o0.x = (a.x-mean)*inv*g0.x + b0.x;  o0.y = (a.y-mean)*inv*g0.y + b0.y;
    o0.z = (a.z-mean)*inv*g0.z + b0.z;  o0.w = (a.w-mean)*inv*g0.w + b0.w;
    o1.x = (c.x-mean)*inv*g1.x + b1.x;  o1.y = (c.y-mean)*inv*g1.y + b1.y;
    o1.z = (c.z-mean)*inv*g1.z + b1.z;  o1.w = (c.w-mean)*inv*g1.w + b1.w;
    float4* op = (float4*)(g_win + r * 256);
    op[lane*2] = o0; op[lane*2+1] = o1;
}

// ---------------- windowed attention: one block per (window, head) ----------------
__global__ __launch_bounds__(64) void k_attn(const float* __restrict__ rpb, int shift) {
    int w = blockIdx.x >> 3, h = blockIdx.x & 7;
    int n = threadIdx.x;                       // 0..63 (query row)
    __shared__ float sk[64][36];
    __shared__ float sv[64][36];
    __shared__ float srpb[343];
    __shared__ int   slab[64];

    const float* row = g_qkv + (w * 64 + n) * 768 + h * 32;
    #pragma unroll
    for (int j = 0; j < 8; j++) {
        *(float4*)&sk[n][j*4] = *(const float4*)(row + 256 + j*4);
        *(float4*)&sv[n][j*4] = *(const float4*)(row + 512 + j*4);
    }
    float q[32];
    #pragma unroll
    for (int j = 0; j < 8; j++) {
        float4 qv = *(const float4*)(row + j*4);
        q[j*4+0] = qv.x * 0.17677669529663687f;
        q[j*4+1] = qv.y * 0.17677669529663687f;
        q[j*4+2] = qv.z * 0.17677669529663687f;
        q[j*4+3] = qv.w * 0.17677669529663687f;
    }
    for (int i = n; i < 343; i += 64) srpb[i] = rpb[i*8 + h];
    {
        // region label in the rolled frame (Swin shifted-window mask)
        int gh = ((w >> 6) << 2)       + (n >> 4);
        int gw = (((w >> 3) & 7) << 2) + ((n >> 2) & 3);
        int gt = ((w & 7) << 2)        + (n & 3);
        int rh = (gh < 28) ? 0 : ((gh < 30) ? 1 : 2);
        int rw = (gw < 28) ? 0 : ((gw < 30) ? 1 : 2);
        int rt = (gt < 28) ? 0 : ((gt < 30) ? 1 : 2);
        slab[n] = rh * 9 + rw * 3 + rt;
    }
    __syncthreads();

    int ch = n >> 4, cw = (n >> 2) & 3, ct = n & 3;
    int mylab = slab[n];
    float p[64];
    float mx = -1e30f;
    #pragma unroll
    for (int m = 0; m < 64; m++) {
        float d = 0.f;
        #pragma unroll
        for (int j = 0; j < 32; j++) d += q[j] * sk[m][j];
        int dh = ch - (m >> 4) + 3;
        int dw = cw - ((m >> 2) & 3) + 3;
        int dt = ct - (m & 3) + 3;
        d += srpb[(dh*7 + dw)*7 + dt];
        if (shift && slab[m] != mylab) d -= 100.f;
        p[m] = d;
        mx = fmaxf(mx, d);
    }
    float sum = 0.f;
    #pragma unroll
    for (int m = 0; m < 64; m++) { p[m] = expf(p[m] - mx); sum += p[m]; }
    float inv = 1.f / sum;
    float acc[32];
    #pragma unroll
    for (int j = 0; j < 32; j++) acc[j] = 0.f;
    #pragma unroll
    for (int m = 0; m < 64; m++) {
        float pm = p[m] * inv;
        #pragma unroll
        for (int j = 0; j < 32; j++) acc[j] += pm * sv[m][j];
    }
    float* op = g_att + (w*64 + n) * 256 + h * 32;
    #pragma unroll
    for (int j = 0; j < 8; j++) {
        float4 o;
        o.x = acc[j*4+0]; o.y = acc[j*4+1]; o.z = acc[j*4+2]; o.w = acc[j*4+3];
        *(float4*)(op + j*4) = o;
    }
}

// ---------------- fp32 NT GEMM: C[M,N] = A[M,K] * B[N,K]^T + bias, epilogues ----------------
// EPI 0: store   1: GELU store   2: scatter-add residual (proj, reverse-partition)   3: add residual (fc2)
template<int EPI>
__global__ __launch_bounds__(256) void k_gemm(const float* __restrict__ A,
                                              const float* __restrict__ B,
                                              const float* __restrict__ bias,
                                              float* __restrict__ Cout,
                                              int N, int K, int shift) {
    __shared__ float As[8][128];
    __shared__ float Bs[8][128];
    int t = threadIdx.x;
    int rowBase = blockIdx.y << 7;
    int colBase = blockIdx.x << 7;
    int ldRow = t >> 1, ldK = (t & 1) << 2;
    const float* Ap = A + (long)(rowBase + ldRow) * K + ldK;
    const float* Bp = B + (long)(colBase + ldRow) * K + ldK;
    int tx = t & 15, ty = t >> 4;
    float acc[8][8];
    #pragma unroll
    for (int i = 0; i < 8; i++)
        #pragma unroll
        for (int j = 0; j < 8; j++) acc[i][j] = 0.f;

    for (int k0 = 0; k0 < K; k0 += 8) {
        float4 av = *(const float4*)(Ap + k0);
        float4 bv = *(const float4*)(Bp + k0);
        __syncthreads();
        As[ldK+0][ldRow] = av.x; As[ldK+1][ldRow] = av.y;
        As[ldK+2][ldRow] = av.z; As[ldK+3][ldRow] = av.w;
        Bs[ldK+0][ldRow] = bv.x; Bs[ldK+1][ldRow] = bv.y;
        Bs[ldK+2][ldRow] = bv.z; Bs[ldK+3][ldRow] = bv.w;
        __syncthreads();
        #pragma unroll
        for (int k = 0; k < 8; k++) {
            float ra[8], rb[8];
            *(float4*)&ra[0] = *(const float4*)&As[k][ty*8];
            *(float4*)&ra[4] = *(const float4*)&As[k][ty*8+4];
            *(float4*)&rb[0] = *(const float4*)&Bs[k][tx*8];
            *(float4*)&rb[4] = *(const float4*)&Bs[k][tx*8+4];
            #pragma unroll
            for (int i = 0; i < 8; i++)
                #pragma unroll
                for (int j = 0; j < 8; j++)
                    acc[i][j] += ra[i] * rb[j];
        }
    }

    int col0 = colBase + tx * 8;
    #pragma unroll
    for (int i = 0; i < 8; i++) {
        int row = rowBase + ty * 8 + i;
        float v[8];
        #pragma unroll
        for (int j = 0; j < 8; j++) v[j] = acc[i][j] + bias[col0 + j];
        if (EPI == 1) {
            #pragma unroll
            for (int j = 0; j < 8; j++)
                v[j] = 0.5f * v[j] * (1.0f + erff(v[j] * 0.70710678118654752f));
        }
        if (EPI == 0 || EPI == 1) {
            float4* cp = (float4*)(Cout + (long)row * N + col0);
            float4 c0, c1;
            c0.x=v[0]; c0.y=v[1]; c0.z=v[2]; c0.w=v[3];
            c1.x=v[4]; c1.y=v[5]; c1.z=v[6]; c1.w=v[7];
            cp[0] = c0; cp[1] = c1;
        } else {
            int dst = (EPI == 2) ? win_to_tok(row, shift) : row;
            float4* rp = (float4*)(g_x + dst * 256 + col0);
            float4 r0 = rp[0], r1 = rp[1];
            r0.x += v[0]; r0.y += v[1]; r0.z += v[2]; r0.w += v[3];
            r1.x += v[4]; r1.y += v[5]; r1.z += v[6]; r1.w += v[7];
            rp[0] = r0; rp[1] = r1;
        }
    }
}

// ---------------- final LN + [L,C] -> [C,L] transpose ----------------
__global__ __launch_bounds__(256) void k_final(const float* __restrict__ gam,
                                               const float* __restrict__ bet,
                                               float* __restrict__ out) {
    __shared__ float sm[256][33];
    int warp = threadIdx.x >> 5, lane = threadIdx.x & 31;
    int l0 = blockIdx.x << 5;
    float4 g0 = ((const float4*)gam)[lane*2], g1 = ((const float4*)gam)[lane*2+1];
    float4 b0 = ((const float4*)bet)[lane*2], b1 = ((const float4*)bet)[lane*2+1];
    #pragma unroll
    for (int i = 0; i < 4; i++) {
        int tok = (warp << 2) + i;
        const float4* xp = (const float4*)(g_x + (l0 + tok) * 256);
        float4 a = xp[lane*2], c = xp[lane*2+1];
        float s  = a.x + a.y + a.z + a.w + c.x + c.y + c.z + c.w;
        float sq = a.x*a.x + a.y*a.y + a.z*a.z + a.w*a.w
                 + c.x*c.x + c.y*c.y + c.z*c.z + c.w*c.w;
        #pragma unroll
        for (int o = 16; o; o >>= 1) {
            s  += __shfl_xor_sync(0xffffffffu, s, o);
            sq += __shfl_xor_sync(0xffffffffu, sq, o);
        }
        float mean = s * (1.0f / 256.0f);
        float inv = rsqrtf(sq * (1.0f / 256.0f) - mean * mean + 1e-5f);
        int cb = lane * 8;
        sm[cb+0][tok] = (a.x-mean)*inv*g0.x + b0.x;
        sm[cb+1][tok] = (a.y-mean)*inv*g0.y + b0.y;
        sm[cb+2][tok] = (a.z-mean)*inv*g0.z + b0.z;
        sm[cb+3][tok] = (a.w-mean)*inv*g0.w + b0.w;
        sm[cb+4][tok] = (c.x-mean)*inv*g1.x + b1.x;
        sm[cb+5][tok] = (c.y-mean)*inv*g1.y + b1.y;
        sm[cb+6][tok] = (c.z-mean)*inv*g1.z + b1.z;
        sm[cb+7][tok] = (c.w-mean)*inv*g1.w + b1.w;
    }
    __syncthreads();
    int lt = threadIdx.x & 31;
    int cw = threadIdx.x >> 5;
    #pragma unroll
    for (int cc = 0; cc < 32; cc++) {
        int c = (cc << 3) + cw;
        out[c * L_TOK + l0 + lt] = sm[c][lt];
    }
}

// ---------------- launch ----------------
extern "C" void kernel_launch(void* const* d_in, const int* in_sizes, int n_in,
                              void* d_out, int out_size) {
    const float* x      = (const float*)d_in[0];
    const float* norm_g = (const float*)d_in[4];
    const float* norm_b = (const float*)d_in[5];
    float* out = (float*)d_out;

    float *p_win, *p_qkv, *p_att, *p_mlp;
    cudaGetSymbolAddress((void**)&p_win, g_win);
    cudaGetSymbolAddress((void**)&p_qkv, g_qkv);
    cudaGetSymbolAddress((void**)&p_att, g_att);
    cudaGetSymbolAddress((void**)&p_mlp, g_mlp);

    k_copy<<<8192, 256>>>(x);

    for (int blk = 0; blk < 2; blk++) {
        int o = 6 + blk * 13;
        int shift = blk ? 2 : 0;
        const float* n1g   = (const float*)d_in[o+0];
        const float* n1b   = (const float*)d_in[o+1];
        const float* qkvw  = (const float*)d_in[o+2];
        const float* qkvb  = (const float*)d_in[o+3];
        const float* rpb   = (const float*)d_in[o+4];
        const float* projw = (const float*)d_in[o+5];
        const float* projb = (const float*)d_in[o+6];
        const float* n2g   = (const float*)d_in[o+7];
        const float* n2b   = (const float*)d_in[o+8];
        const float* fc1w  = (const float*)d_in[o+9];
        const float* fc1b  = (const float*)d_in[o+10];
        const float* fc2w  = (const float*)d_in[o+11];
        const float* fc2b  = (const float*)d_in[o+12];

        k_ln<1><<<4096, 256>>>(n1g, n1b, shift);                                  // LN1 + shift + partition
        k_gemm<0><<<dim3(6, 256), 256>>>(p_win, qkvw, qkvb, p_qkv, 768, 256, 0);  // QKV
        k_attn<<<4096, 64>>>(rpb, shift);                                         // windowed attention
        k_gemm<2><<<dim3(2, 256), 256>>>(p_att, projw, projb, nullptr, 256, 256, shift); // proj + reverse + residual
        k_ln<0><<<4096, 256>>>(n2g, n2b, 0);                                      // LN2
        k_gemm<1><<<dim3(8, 256), 256>>>(p_win, fc1w, fc1b, p_mlp, 1024, 256, 0); // fc1 + GELU
        k_gemm<3><<<dim3(2, 256), 256>>>(p_mlp, fc2w, fc2b, nullptr, 256, 1024, 0); // fc2 + residual
    }

    k_final<<<1024, 256>>>(norm_g, norm_b, out);
}

// round 2
// speedup vs baseline: 1.7722x; 1.7722x over previous
#include <cuda_runtime.h>
#include <math.h>

#define L_TOK 32768

// ---------------- scratch (device globals; no runtime allocation) ----------------
__device__ float g_x  [L_TOK * 256];   // residual stream
__device__ float g_win[L_TOK * 256];   // LN output / partitioned windows
__device__ float g_qkv[L_TOK * 768];   // qkv
__device__ float g_att[L_TOK * 256];   // attention out (window layout)
__device__ float g_mlp[L_TOK * 1024];  // MLP hidden

// window-layout row r -> original token index (handles cyclic shift roll)
__device__ __forceinline__ int win_to_tok(int r, int shift) {
    int w = r >> 6, n = r & 63;
    int h  = ((w >> 6) << 2)        + (n >> 4);
    int wy = (((w >> 3) & 7) << 2)  + ((n >> 2) & 3);
    int t  = ((w & 7) << 2)         + (n & 3);
    h  = (h  + shift) & 31;
    wy = (wy + shift) & 31;
    t  = (t  + shift) & 31;
    return (h << 10) + (wy << 5) + t;
}

__device__ __forceinline__ void cp16(void* s, const void* g) {
    unsigned sa = (unsigned)__cvta_generic_to_shared(s);
    asm volatile("cp.async.cg.shared.global [%0], [%1], 16;\n" :: "r"(sa), "l"(g));
}
__device__ __forceinline__ unsigned f2tf(float x) {
    unsigned u;
    asm("cvt.rna.tf32.f32 %0, %1;" : "=r"(u) : "f"(x));
    return u;
}
__device__ __forceinline__ void mma_tf32(float* d, const unsigned* a, const unsigned* b) {
    asm volatile(
        "mma.sync.aligned.m16n8k8.row.col.f32.tf32.tf32.f32 "
        "{%0,%1,%2,%3}, {%4,%5,%6,%7}, {%8,%9}, {%0,%1,%2,%3};\n"
        : "+f"(d[0]), "+f"(d[1]), "+f"(d[2]), "+f"(d[3])
        : "r"(a[0]), "r"(a[1]), "r"(a[2]), "r"(a[3]), "r"(b[0]), "r"(b[1]));
}

// ---------------- residual init ----------------
__global__ void k_copy(const float* __restrict__ src) {
    int i = blockIdx.x * 256 + threadIdx.x;
    ((float4*)g_x)[i] = ((const float4*)src)[i];
}

// ---------------- LayerNorm (REMAP=1: fused shift+partition gather) ----------------
template<int REMAP>
__global__ __launch_bounds__(256) void k_ln(const float* __restrict__ gam,
                                            const float* __restrict__ bet, int shift) {
    int warp = threadIdx.x >> 5, lane = threadIdx.x & 31;
    int r = (blockIdx.x << 3) + warp;
    int src = REMAP ? win_to_tok(r, shift) : r;
    const float4* xp = (const float4*)(g_x + src * 256);
    float4 a = xp[lane * 2], c = xp[lane * 2 + 1];
    float s  = a.x + a.y + a.z + a.w + c.x + c.y + c.z + c.w;
    float sq = a.x*a.x + a.y*a.y + a.z*a.z + a.w*a.w
             + c.x*c.x + c.y*c.y + c.z*c.z + c.w*c.w;
    #pragma unroll
    for (int o = 16; o; o >>= 1) {
        s  += __shfl_xor_sync(0xffffffffu, s, o);
        sq += __shfl_xor_sync(0xffffffffu, sq, o);
    }
    float mean = s * (1.0f / 256.0f);
    float inv = rsqrtf(sq * (1.0f / 256.0f) - mean * mean + 1e-5f);
    float4 g0 = ((const float4*)gam)[lane*2], g1 = ((const float4*)gam)[lane*2+1];
    float4 b0 = ((const float4*)bet)[lane*2], b1 = ((const float4*)bet)[lane*2+1];
    float4 o0, o1;
    o0.x = (a.x-mean)*inv*g0.x + b0.x;  o0.y = (a.y-mean)*inv*g0.y + b0.y;
    o0.z = (a.z-mean)*inv*g0.z + b0.z;  o0.w = (a.w-mean)*inv*g0.w + b0.w;
    o1.x = (c.x-mean)*inv*g1.x + b1.x;  o1.y = (c.y-mean)*inv*g1.y + b1.y;
    o1.z = (c.z-mean)*inv*g1.z + b1.z;  o1.w = (c.w-mean)*inv*g1.w + b1.w;
    float4* op = (float4*)(g_win + r * 256);
    op[lane*2] = o0; op[lane*2+1] = o1;
}

// ---------------- windowed attention: one block per (window, head) ----------------
__global__ __launch_bounds__(64) void k_attn(const float* __restrict__ rpb, int shift) {
    int w = blockIdx.x >> 3, h = blockIdx.x & 7;
    int n = threadIdx.x;
    __shared__ float sk[64][36];
    __shared__ float sv[64][36];
    __shared__ float srpb[343];
    __shared__ int   slab[64];

    const float* row = g_qkv + (w * 64 + n) * 768 + h * 32;
    #pragma unroll
    for (int j = 0; j < 8; j++) {
        *(float4*)&sk[n][j*4] = *(const float4*)(row + 256 + j*4);
        *(float4*)&sv[n][j*4] = *(const float4*)(row + 512 + j*4);
    }
    float q[32];
    #pragma unroll
    for (int j = 0; j < 8; j++) {
        float4 qv = *(const float4*)(row + j*4);
        q[j*4+0] = qv.x * 0.17677669529663687f;
        q[j*4+1] = qv.y * 0.17677669529663687f;
        q[j*4+2] = qv.z * 0.17677669529663687f;
        q[j*4+3] = qv.w * 0.17677669529663687f;
    }
    for (int i = n; i < 343; i += 64) srpb[i] = rpb[i*8 + h];
    {
        int gh = ((w >> 6) << 2)       + (n >> 4);
        int gw = (((w >> 3) & 7) << 2) + ((n >> 2) & 3);
        int gt = ((w & 7) << 2)        + (n & 3);
        int rh = (gh < 28) ? 0 : ((gh < 30) ? 1 : 2);
        int rw = (gw < 28) ? 0 : ((gw < 30) ? 1 : 2);
        int rt = (gt < 28) ? 0 : ((gt < 30) ? 1 : 2);
        slab[n] = rh * 9 + rw * 3 + rt;
    }
    __syncthreads();

    int ch = n >> 4, cw = (n >> 2) & 3, ct = n & 3;
    int mylab = slab[n];
    float p[64];
    float mx = -1e30f;
    #pragma unroll
    for (int m = 0; m < 64; m++) {
        float d = 0.f;
        #pragma unroll
        for (int j = 0; j < 32; j++) d += q[j] * sk[m][j];
        int dh = ch - (m >> 4) + 3;
        int dw = cw - ((m >> 2) & 3) + 3;
        int dt = ct - (m & 3) + 3;
        d += srpb[(dh*7 + dw)*7 + dt];
        if (shift && slab[m] != mylab) d -= 100.f;
        p[m] = d;
        mx = fmaxf(mx, d);
    }
    float sum = 0.f;
    #pragma unroll
    for (int m = 0; m < 64; m++) { p[m] = expf(p[m] - mx); sum += p[m]; }
    float inv = 1.f / sum;
    float acc[32];
    #pragma unroll
    for (int j = 0; j < 32; j++) acc[j] = 0.f;
    #pragma unroll
    for (int m = 0; m < 64; m++) {
        float pm = p[m] * inv;
        #pragma unroll
        for (int j = 0; j < 32; j++) acc[j] += pm * sv[m][j];
    }
    float* op = g_att + (w*64 + n) * 256 + h * 32;
    #pragma unroll
    for (int j = 0; j < 8; j++) {
        float4 o;
        o.x = acc[j*4+0]; o.y = acc[j*4+1]; o.z = acc[j*4+2]; o.w = acc[j*4+3];
        *(float4*)(op + j*4) = o;
    }
}

// ---------------- tf32 tensor-core NT GEMM: C[M,N] = A[M,K]*B[N,K]^T + bias ----------------
// Block 128x128, 4 warps of 64x64, K-tile 16, double-buffered cp.async.
// SMEM stored in mma-fragment order [tile][kstep][reg][lane] for conflict-free access.
// EPI 0: store  1: GELU store  2: scatter-add residual (proj)  3: add residual (fc2)
template<int EPI>
__global__ __launch_bounds__(128, 2) void k_gemm(const float* __restrict__ A,
                                                 const float* __restrict__ B,
                                                 const float* __restrict__ bias,
                                                 float* __restrict__ Cout,
                                                 int N, int K, int shift) {
    __shared__ float As[2][2048];   // 8 mt * 2 ks * 4 reg * 32 lane
    __shared__ float Bs[2][2048];   // 16 nt * 2 ks * 2 reg * 32 lane
    const int t = threadIdx.x;
    const int lane = t & 31, wid = t >> 5;
    const int warp_m = wid & 1, warp_n = wid >> 1;
    const int rowBase = blockIdx.y << 7;
    const int colBase = blockIdx.x << 7;

    float acc[4][8][4];
    #pragma unroll
    for (int mt = 0; mt < 4; mt++)
        #pragma unroll
        for (int nt = 0; nt < 8; nt++)
            #pragma unroll
            for (int r = 0; r < 4; r++) acc[mt][nt][r] = 0.f;

    auto load_tile = [&](int buf, int k0) {
        #pragma unroll
        for (int j = 0; j < 4; j++) {
            int q = t + j * 128;              // A: 512 chunks of 16B
            int r = q >> 2, cg = q & 3;
            int ks = cg >> 1, reg = ((r >> 3) & 1) | ((cg & 1) << 1);
            int off = (((r >> 4) * 2 + ks) * 4 + reg) * 32 + (r & 7) * 4;
            cp16(&As[buf][off], A + (size_t)(rowBase + r) * K + k0 + cg * 4);
        }
        #pragma unroll
        for (int j = 0; j < 4; j++) {
            int q = t + j * 128;              // B: 512 chunks
            int n = q >> 2, cg = q & 3;
            int ks = cg >> 1, reg = cg & 1;
            int off = (((n >> 3) * 2 + ks) * 2 + reg) * 32 + (n & 7) * 4;
            cp16(&Bs[buf][off], B + (size_t)(colBase + n) * K + k0 + cg * 4);
        }
        asm volatile("cp.async.commit_group;\n" ::: "memory");
    };

    const int ntiles = K >> 4;
    load_tile(0, 0);
    for (int i = 0; i < ntiles; i++) {
        if (i + 1 < ntiles) {
            load_tile((i + 1) & 1, (i + 1) << 4);
            asm volatile("cp.async.wait_group 1;\n" ::: "memory");
        } else {
            asm volatile("cp.async.wait_group 0;\n" ::: "memory");
        }
        __syncthreads();
        const int buf = i & 1;
        #pragma unroll
        for (int ks = 0; ks < 2; ks++) {
            unsigned af[4][4], bf[8][2];
            #pragma unroll
            for (int mt = 0; mt < 4; mt++) {
                int base = (((warp_m * 4 + mt) * 2 + ks) * 4) * 32 + lane;
                #pragma unroll
                for (int r = 0; r < 4; r++) af[mt][r] = f2tf(As[buf][base + r * 32]);
            }
            #pragma unroll
            for (int nt = 0; nt < 8; nt++) {
                int base = (((warp_n * 8 + nt) * 2 + ks) * 2) * 32 + lane;
                #pragma unroll
                for (int r = 0; r < 2; r++) bf[nt][r] = f2tf(Bs[buf][base + r * 32]);
            }
            #pragma unroll
            for (int mt = 0; mt < 4; mt++)
                #pragma unroll
                for (int nt = 0; nt < 8; nt++)
                    mma_tf32(acc[mt][nt], af[mt], bf[nt]);
        }
        __syncthreads();
    }

    // epilogue
    #pragma unroll
    for (int mt = 0; mt < 4; mt++) {
        #pragma unroll
        for (int i = 0; i < 2; i++) {
            int row = rowBase + warp_m * 64 + mt * 16 + (lane >> 2) + i * 8;
            int dst = (EPI == 2) ? win_to_tok(row, shift) : row;
            #pragma unroll
            for (int nt = 0; nt < 8; nt++) {
                int col = colBase + warp_n * 64 + nt * 8 + (lane & 3) * 2;
                float v0 = acc[mt][nt][i * 2 + 0] + bias[col];
                float v1 = acc[mt][nt][i * 2 + 1] + bias[col + 1];
                if (EPI == 1) {
                    v0 = 0.5f * v0 * (1.0f + erff(v0 * 0.70710678118654752f));
                    v1 = 0.5f * v1 * (1.0f + erff(v1 * 0.70710678118654752f));
                }
                if (EPI == 0 || EPI == 1) {
                    float2 o; o.x = v0; o.y = v1;
                    *(float2*)(Cout + (size_t)row * N + col) = o;
                } else {
                    float2* rp = (float2*)(g_x + dst * 256 + col);
                    float2 r0 = *rp;
                    r0.x += v0; r0.y += v1;
                    *rp = r0;
                }
            }
        }
    }
}

// ---------------- final LN + [L,C] -> [C,L] transpose ----------------
__global__ __launch_bounds__(256) void k_final(const float* __restrict__ gam,
                                               const float* __restrict__ bet,
                                               float* __restrict__ out) {
    __shared__ float sm[256][33];
    int warp = threadIdx.x >> 5, lane = threadIdx.x & 31;
    int l0 = blockIdx.x << 5;
    float4 g0 = ((const float4*)gam)[lane*2], g1 = ((const float4*)gam)[lane*2+1];
    float4 b0 = ((const float4*)bet)[lane*2], b1 = ((const float4*)bet)[lane*2+1];
    #pragma unroll
    for (int i = 0; i < 4; i++) {
        int tok = (warp << 2) + i;
        const float4* xp = (const float4*)(g_x + (l0 + tok) * 256);
        float4 a = xp[lane*2], c = xp[lane*2+1];
        float s  = a.x + a.y + a.z + a.w + c.x + c.y + c.z + c.w;
        float sq = a.x*a.x + a.y*a.y + a.z*a.z + a.w*a.w
                 + c.x*c.x + c.y*c.y + c.z*c.z + c.w*c.w;
        #pragma unroll
        for (int o = 16; o; o >>= 1) {
            s  += __shfl_xor_sync(0xffffffffu, s, o);
            sq += __shfl_xor_sync(0xffffffffu, sq, o);
        }
        float mean = s * (1.0f / 256.0f);
        float inv = rsqrtf(sq * (1.0f / 256.0f) - mean * mean + 1e-5f);
        int cb = lane * 8;
        sm[cb+0][tok] = (a.x-mean)*inv*g0.x + b0.x;
        sm[cb+1][tok] = (a.y-mean)*inv*g0.y + b0.y;
        sm[cb+2][tok] = (a.z-mean)*inv*g0.z + b0.z;
        sm[cb+3][tok] = (a.w-mean)*inv*g0.w + b0.w;
        sm[cb+4][tok] = (c.x-mean)*inv*g1.x + b1.x;
        sm[cb+5][tok] = (c.y-mean)*inv*g1.y + b1.y;
        sm[cb+6][tok] = (c.z-mean)*inv*g1.z + b1.z;
        sm[cb+7][tok] = (c.w-mean)*inv*g1.w + b1.w;
    }
    __syncthreads();
    int lt = threadIdx.x & 31;
    int cw = threadIdx.x >> 5;
    #pragma unroll
    for (int cc = 0; cc < 32; cc++) {
        int c = (cc << 3) + cw;
        out[c * L_TOK + l0 + lt] = sm[c][lt];
    }
}

// ---------------- launch ----------------
extern "C" void kernel_launch(void* const* d_in, const int* in_sizes, int n_in,
                              void* d_out, int out_size) {
    const float* x      = (const float*)d_in[0];
    const float* norm_g = (const float*)d_in[4];
    const float* norm_b = (const float*)d_in[5];
    float* out = (float*)d_out;

    float *p_win, *p_qkv, *p_att, *p_mlp;
    cudaGetSymbolAddress((void**)&p_win, g_win);
    cudaGetSymbolAddress((void**)&p_qkv, g_qkv);
    cudaGetSymbolAddress((void**)&p_att, g_att);
    cudaGetSymbolAddress((void**)&p_mlp, g_mlp);

    k_copy<<<8192, 256>>>(x);

    for (int blk = 0; blk < 2; blk++) {
        int o = 6 + blk * 13;
        int shift = blk ? 2 : 0;
        const float* n1g   = (const float*)d_in[o+0];
        const float* n1b   = (const float*)d_in[o+1];
        const float* qkvw  = (const float*)d_in[o+2];
        const float* qkvb  = (const float*)d_in[o+3];
        const float* rpb   = (const float*)d_in[o+4];
        const float* projw = (const float*)d_in[o+5];
        const float* projb = (const float*)d_in[o+6];
        const float* n2g   = (const float*)d_in[o+7];
        const float* n2b   = (const float*)d_in[o+8];
        const float* fc1w  = (const float*)d_in[o+9];
        const float* fc1b  = (const float*)d_in[o+10];
        const float* fc2w  = (const float*)d_in[o+11];
        const float* fc2b  = (const float*)d_in[o+12];

        k_ln<1><<<4096, 256>>>(n1g, n1b, shift);                                   // LN1 + shift + partition
        k_gemm<0><<<dim3(6, 256), 128>>>(p_win, qkvw, qkvb, p_qkv, 768, 256, 0);   // QKV
        k_attn<<<4096, 64>>>(rpb, shift);                                          // windowed attention
        k_gemm<2><<<dim3(2, 256), 128>>>(p_att, projw, projb, nullptr, 256, 256, shift); // proj + residual
        k_ln<0><<<4096, 256>>>(n2g, n2b, 0);                                       // LN2
        k_gemm<1><<<dim3(8, 256), 128>>>(p_win, fc1w, fc1b, p_mlp, 1024, 256, 0);  // fc1 + GELU
        k_gemm<3><<<dim3(2, 256), 128>>>(p_mlp, fc2w, fc2b, nullptr, 256, 1024, 0); // fc2 + residual
    }

    k_final<<<1024, 256>>>(norm_g, norm_b, out);
}

// round 3
// speedup vs baseline: 1.8622x; 1.0508x over previous
#include <cuda_runtime.h>
#include <math.h>

#define L_TOK 32768

// ---------------- scratch (device globals; no runtime allocation) ----------------
__device__ float g_x  [L_TOK * 256];   // residual stream
__device__ float g_win[L_TOK * 256];   // LN output / partitioned windows (tf32-rounded)
__device__ float g_qkv[L_TOK * 768];   // qkv (fp32)
__device__ float g_att[L_TOK * 256];   // attention out (tf32-rounded)
__device__ float g_mlp[L_TOK * 1024];  // MLP hidden (tf32-rounded)
__device__ float g_wbuf[2 * 786432];   // tf32-rounded weights

__device__ __forceinline__ int win_to_tok(int r, int shift) {
    int w = r >> 6, n = r & 63;
    int h  = ((w >> 6) << 2)        + (n >> 4);
    int wy = (((w >> 3) & 7) << 2)  + ((n >> 2) & 3);
    int t  = ((w & 7) << 2)         + (n & 3);
    h  = (h  + shift) & 31;
    wy = (wy + shift) & 31;
    t  = (t  + shift) & 31;
    return (h << 10) + (wy << 5) + t;
}

__device__ __forceinline__ void cp16(void* s, const void* g) {
    unsigned sa = (unsigned)__cvta_generic_to_shared(s);
    asm volatile("cp.async.cg.shared.global [%0], [%1], 16;\n" :: "r"(sa), "l"(g));
}
__device__ __forceinline__ unsigned f2tf(float x) {
    unsigned u;
    asm("cvt.rna.tf32.f32 %0, %1;" : "=r"(u) : "f"(x));
    return u;
}
__device__ __forceinline__ float rndf(float x) { return __uint_as_float(f2tf(x)); }

__device__ __forceinline__ void mma_tf32(float* d, const unsigned* a, const unsigned* b) {
    asm volatile(
        "mma.sync.aligned.m16n8k8.row.col.f32.tf32.tf32.f32 "
        "{%0,%1,%2,%3}, {%4,%5,%6,%7}, {%8,%9}, {%0,%1,%2,%3};\n"
        : "+f"(d[0]), "+f"(d[1]), "+f"(d[2]), "+f"(d[3])
        : "r"(a[0]), "r"(a[1]), "r"(a[2]), "r"(a[3]), "r"(b[0]), "r"(b[1]));
}

// ---------------- residual init ----------------
__global__ void k_copy(const float* __restrict__ src) {
    int i = blockIdx.x * 256 + threadIdx.x;
    ((float4*)g_x)[i] = ((const float4*)src)[i];
}

// ---------------- tf32 weight pre-rounding ----------------
__global__ void k_round(const float* __restrict__ src, float* __restrict__ dst, int n4) {
    int i = blockIdx.x * 256 + threadIdx.x;
    if (i < n4) {
        float4 v = ((const float4*)src)[i];
        v.x = rndf(v.x); v.y = rndf(v.y); v.z = rndf(v.z); v.w = rndf(v.w);
        ((float4*)dst)[i] = v;
    }
}

// ---------------- LayerNorm (REMAP=1: fused shift+partition gather); tf32-rounded out ----------------
template<int REMAP>
__global__ __launch_bounds__(256) void k_ln(const float* __restrict__ gam,
                                            const float* __restrict__ bet, int shift) {
    int warp = threadIdx.x >> 5, lane = threadIdx.x & 31;
    int r = (blockIdx.x << 3) + warp;
    int src = REMAP ? win_to_tok(r, shift) : r;
    const float4* xp = (const float4*)(g_x + src * 256);
    float4 a = xp[lane * 2], c = xp[lane * 2 + 1];
    float s  = a.x + a.y + a.z + a.w + c.x + c.y + c.z + c.w;
    float sq = a.x*a.x + a.y*a.y + a.z*a.z + a.w*a.w
             + c.x*c.x + c.y*c.y + c.z*c.z + c.w*c.w;
    #pragma unroll
    for (int o = 16; o; o >>= 1) {
        s  += __shfl_xor_sync(0xffffffffu, s, o);
        sq += __shfl_xor_sync(0xffffffffu, sq, o);
    }
    float mean = s * (1.0f / 256.0f);
    float inv = rsqrtf(sq * (1.0f / 256.0f) - mean * mean + 1e-5f);
    float4 g0 = ((const float4*)gam)[lane*2], g1 = ((const float4*)gam)[lane*2+1];
    float4 b0 = ((const float4*)bet)[lane*2], b1 = ((const float4*)bet)[lane*2+1];
    float4 o0, o1;
    o0.x = rndf((a.x-mean)*inv*g0.x + b0.x);  o0.y = rndf((a.y-mean)*inv*g0.y + b0.y);
    o0.z = rndf((a.z-mean)*inv*g0.z + b0.z);  o0.w = rndf((a.w-mean)*inv*g0.w + b0.w);
    o1.x = rndf((c.x-mean)*inv*g1.x + b1.x);  o1.y = rndf((c.y-mean)*inv*g1.y + b1.y);
    o1.z = rndf((c.z-mean)*inv*g1.z + b1.z);  o1.w = rndf((c.w-mean)*inv*g1.w + b1.w);
    float4* op = (float4*)(g_win + r * 256);
    op[lane*2] = o0; op[lane*2+1] = o1;
}

// ---------------- windowed attention: one block per (window, head) ----------------
__global__ __launch_bounds__(64) void k_attn(const float* __restrict__ rpb, int shift) {
    int w = blockIdx.x >> 3, h = blockIdx.x & 7;
    int n = threadIdx.x;
    __shared__ float sk[64][32];
    __shared__ float sv[64][32];
    __shared__ float srpb[343];
    __shared__ int   slab[64];

    const float* row = g_qkv + (w * 64 + n) * 768 + h * 32;
    #pragma unroll
    for (int j = 0; j < 8; j++) {
        *(float4*)&sk[n][j*4] = *(const float4*)(row + 256 + j*4);
        *(float4*)&sv[n][j*4] = *(const float4*)(row + 512 + j*4);
    }
    float q[32];
    #pragma unroll
    for (int j = 0; j < 8; j++) {
        float4 qv = *(const float4*)(row + j*4);
        q[j*4+0] = qv.x * 0.17677669529663687f;
        q[j*4+1] = qv.y * 0.17677669529663687f;
        q[j*4+2] = qv.z * 0.17677669529663687f;
        q[j*4+3] = qv.w * 0.17677669529663687f;
    }
    for (int i = n; i < 343; i += 64) srpb[i] = rpb[i*8 + h];
    {
        int gh = ((w >> 6) << 2)       + (n >> 4);
        int gw = (((w >> 3) & 7) << 2) + ((n >> 2) & 3);
        int gt = ((w & 7) << 2)        + (n & 3);
        int rh = (gh < 28) ? 0 : ((gh < 30) ? 1 : 2);
        int rw = (gw < 28) ? 0 : ((gw < 30) ? 1 : 2);
        int rt = (gt < 28) ? 0 : ((gt < 30) ? 1 : 2);
        slab[n] = rh * 9 + rw * 3 + rt;
    }
    __syncthreads();

    int ch = n >> 4, cw = (n >> 2) & 3, ct = n & 3;
    int mylab = slab[n];
    float p[64];
    float mx = -1e30f;
    #pragma unroll
    for (int m = 0; m < 64; m++) {
        const float4* kp = (const float4*)sk[m];       // broadcast reads
        float d = 0.f;
        #pragma unroll
        for (int j = 0; j < 8; j++) {
            float4 kv = kp[j];
            d += q[j*4+0]*kv.x + q[j*4+1]*kv.y + q[j*4+2]*kv.z + q[j*4+3]*kv.w;
        }
        int dh = ch - (m >> 4) + 3;
        int dw = cw - ((m >> 2) & 3) + 3;
        int dt = ct - (m & 3) + 3;
        d += srpb[(dh*7 + dw)*7 + dt];
        if (shift && slab[m] != mylab) d -= 100.f;
        p[m] = d;
        mx = fmaxf(mx, d);
    }
    float sum = 0.f;
    #pragma unroll
    for (int m = 0; m < 64; m++) { p[m] = __expf(p[m] - mx); sum += p[m]; }
    float inv = 1.f / sum;
    float acc[32];
    #pragma unroll
    for (int j = 0; j < 32; j++) acc[j] = 0.f;
    #pragma unroll
    for (int m = 0; m < 64; m++) {
        float pm = p[m] * inv;
        const float4* vp = (const float4*)sv[m];       // broadcast reads
        #pragma unroll
        for (int j = 0; j < 8; j++) {
            float4 vv = vp[j];
            acc[j*4+0] += pm*vv.x; acc[j*4+1] += pm*vv.y;
            acc[j*4+2] += pm*vv.z; acc[j*4+3] += pm*vv.w;
        }
    }
    float* op = g_att + (w*64 + n) * 256 + h * 32;
    #pragma unroll
    for (int j = 0; j < 8; j++) {
        float4 o;
        o.x = rndf(acc[j*4+0]); o.y = rndf(acc[j*4+1]);
        o.z = rndf(acc[j*4+2]); o.w = rndf(acc[j*4+3]);
        *(float4*)(op + j*4) = o;
    }
}

// ---------------- tf32 tensor-core NT GEMM: C = A*B^T + bias ----------------
// Inputs pre-rounded to tf32. Block 128x128, 4 warps of 64x64, K-tile 16,
// 3-stage cp.async pipeline, single __syncthreads per tile.
// EPI 0: store  1: GELU store (rounded)  2: scatter-add residual  3: add residual
template<int EPI>
__global__ __launch_bounds__(128, 2) void k_gemm(const float* __restrict__ A,
                                                 const float* __restrict__ B,
                                                 const float* __restrict__ bias,
                                                 float* __restrict__ Cout,
                                                 int N, int K, int shift) {
    __shared__ float As[3][2048];
    __shared__ float Bs[3][2048];
    const int t = threadIdx.x;
    const int lane = t & 31, wid = t >> 5;
    const int warp_m = wid & 1, warp_n = wid >> 1;
    const int rowBase = blockIdx.y << 7;
    const int colBase = blockIdx.x << 7;

    float acc[4][8][4];
    #pragma unroll
    for (int mt = 0; mt < 4; mt++)
        #pragma unroll
        for (int nt = 0; nt < 8; nt++)
            #pragma unroll
            for (int r = 0; r < 4; r++) acc[mt][nt][r] = 0.f;

    auto load_tile = [&](int buf, int k0) {
        #pragma unroll
        for (int j = 0; j < 4; j++) {
            int q = t + j * 128;
            int r = q >> 2, cg = q & 3;
            int ks = cg >> 1, reg = ((r >> 3) & 1) | ((cg & 1) << 1);
            int off = (((r >> 4) * 2 + ks) * 4 + reg) * 32 + (r & 7) * 4;
            cp16(&As[buf][off], A + (size_t)(rowBase + r) * K + k0 + cg * 4);
        }
        #pragma unroll
        for (int j = 0; j < 4; j++) {
            int q = t + j * 128;
            int n = q >> 2, cg = q & 3;
            int ks = cg >> 1, reg = cg & 1;
            int off = (((n >> 3) * 2 + ks) * 2 + reg) * 32 + (n & 7) * 4;
            cp16(&Bs[buf][off], B + (size_t)(colBase + n) * K + k0 + cg * 4);
        }
        asm volatile("cp.async.commit_group;\n" ::: "memory");
    };

    const int ntiles = K >> 4;
    load_tile(0, 0);
    load_tile(1, 16);
    for (int i = 0; i < ntiles; i++) {
        asm volatile("cp.async.wait_group 1;\n" ::: "memory");
        __syncthreads();
        if (i + 2 < ntiles) load_tile((i + 2) % 3, (i + 2) << 4);
        const int buf = i % 3;
        #pragma unroll
        for (int ks = 0; ks < 2; ks++) {
            unsigned af[4][4], bf[8][2];
            #pragma unroll
            for (int mt = 0; mt < 4; mt++) {
                int base = (((warp_m * 4 + mt) * 2 + ks) * 4) * 32 + lane;
                #pragma unroll
                for (int r = 0; r < 4; r++) af[mt][r] = __float_as_uint(As[buf][base + r * 32]);
            }
            #pragma unroll
            for (int nt = 0; nt < 8; nt++) {
                int base = (((warp_n * 8 + nt) * 2 + ks) * 2) * 32 + lane;
                #pragma unroll
                for (int r = 0; r < 2; r++) bf[nt][r] = __float_as_uint(Bs[buf][base + r * 32]);
            }
            #pragma unroll
            for (int mt = 0; mt < 4; mt++)
                #pragma unroll
                for (int nt = 0; nt < 8; nt++)
                    mma_tf32(acc[mt][nt], af[mt], bf[nt]);
        }
    }

    // epilogue (bias hoisted)
    float2 bv[8];
    #pragma unroll
    for (int nt = 0; nt < 8; nt++)
        bv[nt] = *(const float2*)(bias + colBase + warp_n * 64 + nt * 8 + (lane & 3) * 2);

    #pragma unroll
    for (int mt = 0; mt < 4; mt++) {
        #pragma unroll
        for (int i = 0; i < 2; i++) {
            int row = rowBase + warp_m * 64 + mt * 16 + (lane >> 2) + i * 8;
            int dst = (EPI == 2) ? win_to_tok(row, shift) : row;
            #pragma unroll
            for (int nt = 0; nt < 8; nt++) {
                int col = colBase + warp_n * 64 + nt * 8 + (lane & 3) * 2;
                float v0 = acc[mt][nt][i * 2 + 0] + bv[nt].x;
                float v1 = acc[mt][nt][i * 2 + 1] + bv[nt].y;
                if (EPI == 1) {
                    v0 = rndf(0.5f * v0 * (1.0f + erff(v0 * 0.70710678118654752f)));
                    v1 = rndf(0.5f * v1 * (1.0f + erff(v1 * 0.70710678118654752f)));
                }
                if (EPI == 0 || EPI == 1) {
                    float2 o; o.x = v0; o.y = v1;
                    *(float2*)(Cout + (size_t)row * N + col) = o;
                } else {
                    float2* rp = (float2*)(g_x + dst * 256 + col);
                    float2 r0 = *rp;
                    r0.x += v0; r0.y += v1;
                    *rp = r0;
                }
            }
        }
    }
}

// ---------------- final LN + [L,C] -> [C,L] transpose ----------------
__global__ __launch_bounds__(256) void k_final(const float* __restrict__ gam,
                                               const float* __restrict__ bet,
                                               float* __restrict__ out) {
    __shared__ float sm[256][33];
    int warp = threadIdx.x >> 5, lane = threadIdx.x & 31;
    int l0 = blockIdx.x << 5;
    float4 g0 = ((const float4*)gam)[lane*2], g1 = ((const float4*)gam)[lane*2+1];
    float4 b0 = ((const float4*)bet)[lane*2], b1 = ((const float4*)bet)[lane*2+1];
    #pragma unroll
    for (int i = 0; i < 4; i++) {
        int tok = (warp << 2) + i;
        const float4* xp = (const float4*)(g_x + (l0 + tok) * 256);
        float4 a = xp[lane*2], c = xp[lane*2+1];
        float s  = a.x + a.y + a.z + a.w + c.x + c.y + c.z + c.w;
        float sq = a.x*a.x + a.y*a.y + a.z*a.z + a.w*a.w
                 + c.x*c.x + c.y*c.y + c.z*c.z + c.w*c.w;
        #pragma unroll
        for (int o = 16; o; o >>= 1) {
            s  += __shfl_xor_sync(0xffffffffu, s, o);
            sq += __shfl_xor_sync(0xffffffffu, sq, o);
        }
        float mean = s * (1.0f / 256.0f);
        float inv = rsqrtf(sq * (1.0f / 256.0f) - mean * mean + 1e-5f);
        int cb = lane * 8;
        sm[cb+0][tok] = (a.x-mean)*inv*g0.x + b0.x;
        sm[cb+1][tok] = (a.y-mean)*inv*g0.y + b0.y;
        sm[cb+2][tok] = (a.z-mean)*inv*g0.z + b0.z;
        sm[cb+3][tok] = (a.w-mean)*inv*g0.w + b0.w;
        sm[cb+4][tok] = (c.x-mean)*inv*g1.x + b1.x;
        sm[cb+5][tok] = (c.y-mean)*inv*g1.y + b1.y;
        sm[cb+6][tok] = (c.z-mean)*inv*g1.z + b1.z;
        sm[cb+7][tok] = (c.w-mean)*inv*g1.w + b1.w;
    }
    __syncthreads();
    int lt = threadIdx.x & 31;
    int cw = threadIdx.x >> 5;
    #pragma unroll
    for (int cc = 0; cc < 32; cc++) {
        int c = (cc << 3) + cw;
        out[c * L_TOK + l0 + lt] = sm[c][lt];
    }
}

// ---------------- launch ----------------
extern "C" void kernel_launch(void* const* d_in, const int* in_sizes, int n_in,
                              void* d_out, int out_size) {
    const float* x      = (const float*)d_in[0];
    const float* norm_g = (const float*)d_in[4];
    const float* norm_b = (const float*)d_in[5];
    float* out = (float*)d_out;

    float *p_win, *p_qkv, *p_att, *p_mlp, *p_w;
    cudaGetSymbolAddress((void**)&p_win, g_win);
    cudaGetSymbolAddress((void**)&p_qkv, g_qkv);
    cudaGetSymbolAddress((void**)&p_att, g_att);
    cudaGetSymbolAddress((void**)&p_mlp, g_mlp);
    cudaGetSymbolAddress((void**)&p_w,   g_wbuf);

    k_copy<<<8192, 256>>>(x);

    // pre-round weights to tf32
    for (int blk = 0; blk < 2; blk++) {
        int o = 6 + blk * 13;
        float* base = p_w + blk * 786432;
        k_round<<<192, 256>>>((const float*)d_in[o+2],  base,          49152); // qkvw
        k_round<<< 64, 256>>>((const float*)d_in[o+5],  base + 196608, 16384); // projw
        k_round<<<256, 256>>>((const float*)d_in[o+9],  base + 262144, 65536); // fc1w
        k_round<<<256, 256>>>((const float*)d_in[o+11], base + 524288, 65536); // fc2w
    }

    for (int blk = 0; blk < 2; blk++) {
        int o = 6 + blk * 13;
        int shift = blk ? 2 : 0;
        const float* n1g   = (const float*)d_in[o+0];
        const float* n1b   = (const float*)d_in[o+1];
        const float* qkvb  = (const float*)d_in[o+3];
        const float* rpb   = (const float*)d_in[o+4];
        const float* projb = (const float*)d_in[o+6];
        const float* n2g   = (const float*)d_in[o+7];
        const float* n2b   = (const float*)d_in[o+8];
        const float* fc1b  = (const float*)d_in[o+10];
        const float* fc2b  = (const float*)d_in[o+12];
        float* wbase = p_w + blk * 786432;

        k_ln<1><<<4096, 256>>>(n1g, n1b, shift);
        k_gemm<0><<<dim3(6, 256), 128>>>(p_win, wbase,          qkvb,  p_qkv, 768, 256, 0);
        k_attn<<<4096, 64>>>(rpb, shift);
        k_gemm<2><<<dim3(2, 256), 128>>>(p_att, wbase + 196608, projb, nullptr, 256, 256, shift);
        k_ln<0><<<4096, 256>>>(n2g, n2b, 0);
        k_gemm<1><<<dim3(8, 256), 128>>>(p_win, wbase + 262144, fc1b,  p_mlp, 1024, 256, 0);
        k_gemm<3><<<dim3(2, 256), 128>>>(p_mlp, wbase + 524288, fc2b,  nullptr, 256, 1024, 0);
    }

    k_final<<<1024, 256>>>(norm_g, norm_b, out);
}

// round 5
// speedup vs baseline: 2.8317x; 1.5206x over previous
#include <cuda_runtime.h>
#include <cuda_fp16.h>
#include <math.h>

#define L_TOK 32768

// ---------------- scratch (device globals; no runtime allocation) ----------------
__device__ float  g_x  [L_TOK * 256];   // residual stream (fp32)
__device__ __half g_win[L_TOK * 256];   // LN output / partitioned windows (fp16)
__device__ float  g_qkv[L_TOK * 768];   // qkv (fp32)
__device__ __half g_att[L_TOK * 256];   // attention out (fp16, window layout)
__device__ __half g_mlp[L_TOK * 1024];  // MLP hidden (fp16)
__device__ __half g_wbuf[2 * 786432];   // fp16 weights

__device__ __forceinline__ int win_to_tok(int r, int shift) {
    int w = r >> 6, n = r & 63;
    int h  = ((w >> 6) << 2)        + (n >> 4);
    int wy = (((w >> 3) & 7) << 2)  + ((n >> 2) & 3);
    int t  = ((w & 7) << 2)         + (n & 3);
    h  = (h  + shift) & 31;
    wy = (wy + shift) & 31;
    t  = (t  + shift) & 31;
    return (h << 10) + (wy << 5) + t;
}

__device__ __forceinline__ void cp16(void* s, const void* g) {
    unsigned sa = (unsigned)__cvta_generic_to_shared(s);
    asm volatile("cp.async.cg.shared.global [%0], [%1], 16;\n" :: "r"(sa), "l"(g));
}
__device__ __forceinline__ void mma_f16(float* d, const unsigned* a, const unsigned* b) {
    asm volatile(
        "mma.sync.aligned.m16n8k16.row.col.f32.f16.f16.f32 "
        "{%0,%1,%2,%3}, {%4,%5,%6,%7}, {%8,%9}, {%0,%1,%2,%3};\n"
        : "+f"(d[0]), "+f"(d[1]), "+f"(d[2]), "+f"(d[3])
        : "r"(a[0]), "r"(a[1]), "r"(a[2]), "r"(a[3]), "r"(b[0]), "r"(b[1]));
}
__device__ __forceinline__ unsigned packh2(float a, float b) {
    __half2 h = __floats2half2_rn(a, b);
    return *(unsigned*)&h;
}

// ---------------- residual init ----------------
__global__ void k_copy(const float* __restrict__ src) {
    int i = blockIdx.x * 256 + threadIdx.x;
    ((float4*)g_x)[i] = ((const float4*)src)[i];
}

// ---------------- fp16 weight conversion ----------------
__global__ void k_round(const float* __restrict__ src, __half* __restrict__ dst, int n4) {
    int i = blockIdx.x * 256 + threadIdx.x;
    if (i < n4) {
        float4 v = ((const float4*)src)[i];
        uint2 o;
        o.x = packh2(v.x, v.y);
        o.y = packh2(v.z, v.w);
        ((uint2*)dst)[i] = o;
    }
}

// ---------------- LayerNorm (REMAP=1: fused shift+partition gather); fp16 out ----------------
template<int REMAP>
__global__ __launch_bounds__(256) void k_ln(const float* __restrict__ gam,
                                            const float* __restrict__ bet, int shift) {
    int warp = threadIdx.x >> 5, lane = threadIdx.x & 31;
    int r = (blockIdx.x << 3) + warp;
    int src = REMAP ? win_to_tok(r, shift) : r;
    const float4* xp = (const float4*)(g_x + src * 256);
    float4 a = xp[lane * 2], c = xp[lane * 2 + 1];
    float s  = a.x + a.y + a.z + a.w + c.x + c.y + c.z + c.w;
    float sq = a.x*a.x + a.y*a.y + a.z*a.z + a.w*a.w
             + c.x*c.x + c.y*c.y + c.z*c.z + c.w*c.w;
    #pragma unroll
    for (int o = 16; o; o >>= 1) {
        s  += __shfl_xor_sync(0xffffffffu, s, o);
        sq += __shfl_xor_sync(0xffffffffu, sq, o);
    }
    float mean = s * (1.0f / 256.0f);
    float inv = rsqrtf(sq * (1.0f / 256.0f) - mean * mean + 1e-5f);
    float4 g0 = ((const float4*)gam)[lane*2], g1 = ((const float4*)gam)[lane*2+1];
    float4 b0 = ((const float4*)bet)[lane*2], b1 = ((const float4*)bet)[lane*2+1];
    uint4 o;
    o.x = packh2((a.x-mean)*inv*g0.x + b0.x, (a.y-mean)*inv*g0.y + b0.y);
    o.y = packh2((a.z-mean)*inv*g0.z + b0.z, (a.w-mean)*inv*g0.w + b0.w);
    o.z = packh2((c.x-mean)*inv*g1.x + b1.x, (c.y-mean)*inv*g1.y + b1.y);
    o.w = packh2((c.z-mean)*inv*g1.z + b1.z, (c.w-mean)*inv*g1.w + b1.w);
    ((uint4*)(g_win + r * 256))[lane] = o;
}

// ---------------- windowed attention: one block per (window, head) ----------------
__global__ __launch_bounds__(64) void k_attn(const float* __restrict__ rpb, int shift) {
    int w = blockIdx.x >> 3, h = blockIdx.x & 7;
    int n = threadIdx.x;
    __shared__ float sk[64][32];
    __shared__ float sv[64][32];
    __shared__ float srpb[343];
    __shared__ int   slab[64];

    const float* row = g_qkv + (w * 64 + n) * 768 + h * 32;
    #pragma unroll
    for (int j = 0; j < 8; j++) {
        *(float4*)&sk[n][j*4] = *(const float4*)(row + 256 + j*4);
        *(float4*)&sv[n][j*4] = *(const float4*)(row + 512 + j*4);
    }
    float q[32];
    #pragma unroll
    for (int j = 0; j < 8; j++) {
        float4 qv = *(const float4*)(row + j*4);
        q[j*4+0] = qv.x * 0.17677669529663687f;
        q[j*4+1] = qv.y * 0.17677669529663687f;
        q[j*4+2] = qv.z * 0.17677669529663687f;
        q[j*4+3] = qv.w * 0.17677669529663687f;
    }
    for (int i = n; i < 343; i += 64) srpb[i] = rpb[i*8 + h];
    {
        int gh = ((w >> 6) << 2)       + (n >> 4);
        int gw = (((w >> 3) & 7) << 2) + ((n >> 2) & 3);
        int gt = ((w & 7) << 2)        + (n & 3);
        int rh = (gh < 28) ? 0 : ((gh < 30) ? 1 : 2);
        int rw = (gw < 28) ? 0 : ((gw < 30) ? 1 : 2);
        int rt = (gt < 28) ? 0 : ((gt < 30) ? 1 : 2);
        slab[n] = rh * 9 + rw * 3 + rt;
    }
    __syncthreads();

    int ch = n >> 4, cw = (n >> 2) & 3, ct = n & 3;
    int mylab = slab[n];
    float p[64];
    float mx = -1e30f;
    #pragma unroll
    for (int m = 0; m < 64; m++) {
        const float4* kp = (const float4*)sk[m];
        float d = 0.f;
        #pragma unroll
        for (int j = 0; j < 8; j++) {
            float4 kv = kp[j];
            d += q[j*4+0]*kv.x + q[j*4+1]*kv.y + q[j*4+2]*kv.z + q[j*4+3]*kv.w;
        }
        int dh = ch - (m >> 4) + 3;
        int dw = cw - ((m >> 2) & 3) + 3;
        int dt = ct - (m & 3) + 3;
        d += srpb[(dh*7 + dw)*7 + dt];
        if (shift && slab[m] != mylab) d -= 100.f;
        p[m] = d;
        mx = fmaxf(mx, d);
    }
    float sum = 0.f;
    #pragma unroll
    for (int m = 0; m < 64; m++) { p[m] = __expf(p[m] - mx); sum += p[m]; }
    float inv = 1.f / sum;
    float acc[32];
    #pragma unroll
    for (int j = 0; j < 32; j++) acc[j] = 0.f;
    #pragma unroll
    for (int m = 0; m < 64; m++) {
        float pm = p[m] * inv;
        const float4* vp = (const float4*)sv[m];
        #pragma unroll
        for (int j = 0; j < 8; j++) {
            float4 vv = vp[j];
            acc[j*4+0] += pm*vv.x; acc[j*4+1] += pm*vv.y;
            acc[j*4+2] += pm*vv.z; acc[j*4+3] += pm*vv.w;
        }
    }
    __half* op = g_att + (w*64 + n) * 256 + h * 32;
    #pragma unroll
    for (int u = 0; u < 2; u++) {
        uint4 o;
        o.x = packh2(acc[u*16+0],  acc[u*16+1]);
        o.y = packh2(acc[u*16+2],  acc[u*16+3]);
        o.z = packh2(acc[u*16+4],  acc[u*16+5]);
        o.w = packh2(acc[u*16+6],  acc[u*16+7]);
        ((uint4*)op)[u*2] = o;
        o.x = packh2(acc[u*16+8],  acc[u*16+9]);
        o.y = packh2(acc[u*16+10], acc[u*16+11]);
        o.z = packh2(acc[u*16+12], acc[u*16+13]);
        o.w = packh2(acc[u*16+14], acc[u*16+15]);
        ((uint4*)op)[u*2+1] = o;
    }
}

// ---------------- fp16 tensor-core NT GEMM: C[M,N] = A[M,K]*B[N,K]^T + bias ----------------
// Block 128x128, 4 warps of 64x64, K-tile 32 halves, 3-stage cp.async pipeline.
// SMEM in mma-fragment order [tile][kstep][reg][lane] (half2 elements), conflict-free.
// EPI 0: +bias store fp32   1: +bias GELU store fp16   2: scatter-add residual   3: add residual
template<int EPI, typename OutT>
__global__ __launch_bounds__(128, 2) void k_gemm(const __half* __restrict__ A,
                                                 const __half* __restrict__ B,
                                                 const float* __restrict__ bias,
                                                 OutT* __restrict__ Cout,
                                                 int N, int K, int shift) {
    __shared__ unsigned As[3][2048];   // 8 mt * 2 ks * 4 reg * 32 lane (half2)
    __shared__ unsigned Bs[3][2048];   // 16 nt * 2 ks * 2 reg * 32 lane (half2)
    const int t = threadIdx.x;
    const int lane = t & 31, wid = t >> 5;
    const int warp_m = wid & 1, warp_n = wid >> 1;
    const int rowBase = blockIdx.y << 7;
    const int colBase = blockIdx.x << 7;

    float acc[4][8][4];
    #pragma unroll
    for (int mt = 0; mt < 4; mt++)
        #pragma unroll
        for (int nt = 0; nt < 8; nt++)
            #pragma unroll
            for (int r = 0; r < 4; r++) acc[mt][nt][r] = 0.f;

    auto load_tile = [&](int buf, int k0) {
        #pragma unroll
        for (int j = 0; j < 4; j++) {
            int q = t + j * 128;              // A: 512 chunks of 16B (8 halves)
            int r = q >> 2, cg = q & 3;
            int ks = cg >> 1, reg = ((r >> 3) & 1) | ((cg & 1) << 1);
            int off = (((r >> 4) * 2 + ks) * 4 + reg) * 32 + (r & 7) * 4;
            cp16(&As[buf][off], A + (size_t)(rowBase + r) * K + k0 + cg * 8);
        }
        #pragma unroll
        for (int j = 0; j < 4; j++) {
            int q = t + j * 128;              // B: 512 chunks
            int n = q >> 2, cg = q & 3;
            int ks = cg >> 1, reg = cg & 1;
            int off = (((n >> 3) * 2 + ks) * 2 + reg) * 32 + (n & 7) * 4;
            cp16(&Bs[buf][off], B + (size_t)(colBase + n) * K + k0 + cg * 8);
        }
        asm volatile("cp.async.commit_group;\n" ::: "memory");
    };

    const int ntiles = K >> 5;
    load_tile(0, 0);
    load_tile(1, 32);
    for (int i = 0; i < ntiles; i++) {
        asm volatile("cp.async.wait_group 1;\n" ::: "memory");
        __syncthreads();
        if (i + 2 < ntiles) load_tile((i + 2) % 3, (i + 2) << 5);
        const int buf = i % 3;
        #pragma unroll
        for (int ks = 0; ks < 2; ks++) {
            unsigned af[4][4], bf[8][2];
            #pragma unroll
            for (int mt = 0; mt < 4; mt++) {
                int base = (((warp_m * 4 + mt) * 2 + ks) * 4) * 32 + lane;
                #pragma unroll
                for (int r = 0; r < 4; r++) af[mt][r] = As[buf][base + r * 32];
            }
            #pragma unroll
            for (int nt = 0; nt < 8; nt++) {
                int base = (((warp_n * 8 + nt) * 2 + ks) * 2) * 32 + lane;
                #pragma unroll
                for (int r = 0; r < 2; r++) bf[nt][r] = Bs[buf][base + r * 32];
            }
            #pragma unroll
            for (int mt = 0; mt < 4; mt++)
                #pragma unroll
                for (int nt = 0; nt < 8; nt++)
                    mma_f16(acc[mt][nt], af[mt], bf[nt]);
        }
        __syncthreads();
    }

    // epilogue (bias hoisted)
    float2 bv[8];
    #pragma unroll
    for (int nt = 0; nt < 8; nt++)
        bv[nt] = *(const float2*)(bias + colBase + warp_n * 64 + nt * 8 + (lane & 3) * 2);

    #pragma unroll
    for (int mt = 0; mt < 4; mt++) {
        #pragma unroll
        for (int i = 0; i < 2; i++) {
            int row = rowBase + warp_m * 64 + mt * 16 + (lane >> 2) + i * 8;
            int dst = (EPI == 2) ? win_to_tok(row, shift) : row;
            #pragma unroll
            for (int nt = 0; nt < 8; nt++) {
                int col = colBase + warp_n * 64 + nt * 8 + (lane & 3) * 2;
                float v0 = acc[mt][nt][i * 2 + 0] + bv[nt].x;
                float v1 = acc[mt][nt][i * 2 + 1] + bv[nt].y;
                if (EPI == 0) {
                    float2 o; o.x = v0; o.y = v1;
                    *(float2*)((float*)Cout + (size_t)row * N + col) = o;
                } else if (EPI == 1) {
                    v0 = 0.5f * v0 * (1.0f + erff(v0 * 0.70710678118654752f));
                    v1 = 0.5f * v1 * (1.0f + erff(v1 * 0.70710678118654752f));
                    unsigned h = packh2(v0, v1);
                    *(unsigned*)((__half*)Cout + (size_t)row * N + col) = h;
                } else {
                    float2* rp = (float2*)(g_x + dst * 256 + col);
                    float2 r0 = *rp;
                    r0.x += v0; r0.y += v1;
                    *rp = r0;
                }
            }
        }
    }
}

// ---------------- final LN + [L,C] -> [C,L] transpose ----------------
__global__ __launch_bounds__(256) void k_final(const float* __restrict__ gam,
                                               const float* __restrict__ bet,
                                               float* __restrict__ out) {
    __shared__ float sm[256][33];
    int warp = threadIdx.x >> 5, lane = threadIdx.x & 31;
    int l0 = blockIdx.x << 5;
    float4 g0 = ((const float4*)gam)[lane*2], g1 = ((const float4*)gam)[lane*2+1];
    float4 b0 = ((const float4*)bet)[lane*2], b1 = ((const float4*)bet)[lane*2+1];
    #pragma unroll
    for (int i = 0; i < 4; i++) {
        int tok = (warp << 2) + i;
        const float4* xp = (const float4*)(g_x + (l0 + tok) * 256);
        float4 a = xp[lane*2], c = xp[lane*2+1];
        float s  = a.x + a.y + a.z + a.w + c.x + c.y + c.z + c.w;
        float sq = a.x*a.x + a.y*a.y + a.z*a.z + a.w*a.w
                 + c.x*c.x + c.y*c.y + c.z*c.z + c.w*c.w;
        #pragma unroll
        for (int o = 16; o; o >>= 1) {
            s  += __shfl_xor_sync(0xffffffffu, s, o);
            sq += __shfl_xor_sync(0xffffffffu, sq, o);
        }
        float mean = s * (1.0f / 256.0f);
        float inv = rsqrtf(sq * (1.0f / 256.0f) - mean * mean + 1e-5f);
        int cb = lane * 8;
        sm[cb+0][tok] = (a.x-mean)*inv*g0.x + b0.x;
        sm[cb+1][tok] = (a.y-mean)*inv*g0.y + b0.y;
        sm[cb+2][tok] = (a.z-mean)*inv*g0.z + b0.z;
        sm[cb+3][tok] = (a.w-mean)*inv*g0.w + b0.w;
        sm[cb+4][tok] = (c.x-mean)*inv*g1.x + b1.x;
        sm[cb+5][tok] = (c.y-mean)*inv*g1.y + b1.y;
        sm[cb+6][tok] = (c.z-mean)*inv*g1.z + b1.z;
        sm[cb+7][tok] = (c.w-mean)*inv*g1.w + b1.w;
    }
    __syncthreads();
    int lt = threadIdx.x & 31;
    int cw = threadIdx.x >> 5;
    #pragma unroll
    for (int cc = 0; cc < 32; cc++) {
        int c = (cc << 3) + cw;
        out[c * L_TOK + l0 + lt] = sm[c][lt];
    }
}

// ---------------- launch ----------------
extern "C" void kernel_launch(void* const* d_in, const int* in_sizes, int n_in,
                              void* d_out, int out_size) {
    const float* x      = (const float*)d_in[0];
    const float* norm_g = (const float*)d_in[4];
    const float* norm_b = (const float*)d_in[5];
    float* out = (float*)d_out;

    __half *p_win, *p_att, *p_mlp, *p_w;
    float *p_qkv;
    cudaGetSymbolAddress((void**)&p_win, g_win);
    cudaGetSymbolAddress((void**)&p_qkv, g_qkv);
    cudaGetSymbolAddress((void**)&p_att, g_att);
    cudaGetSymbolAddress((void**)&p_mlp, g_mlp);
    cudaGetSymbolAddress((void**)&p_w,   g_wbuf);

    k_copy<<<8192, 256>>>(x);

    // convert weights to fp16
    for (int blk = 0; blk < 2; blk++) {
        int o = 6 + blk * 13;
        __half* base = p_w + blk * 786432;
        k_round<<<192, 256>>>((const float*)d_in[o+2],  base,          49152); // qkvw
        k_round<<< 64, 256>>>((const float*)d_in[o+5],  base + 196608, 16384); // projw
        k_round<<<256, 256>>>((const float*)d_in[o+9],  base + 262144, 65536); // fc1w
        k_round<<<256, 256>>>((const float*)d_in[o+11], base + 524288, 65536); // fc2w
    }

    for (int blk = 0; blk < 2; blk++) {
        int o = 6 + blk * 13;
        int shift = blk ? 2 : 0;
        const float* n1g   = (const float*)d_in[o+0];
        const float* n1b   = (const float*)d_in[o+1];
        const float* qkvb  = (const float*)d_in[o+3];
        const float* rpb   = (const float*)d_in[o+4];
        const float* projb = (const float*)d_in[o+6];
        const float* n2g   = (const float*)d_in[o+7];
        const float* n2b   = (const float*)d_in[o+8];
        const float* fc1b  = (const float*)d_in[o+10];
        const float* fc2b  = (const float*)d_in[o+12];
        __half* wbase = p_w + blk * 786432;

        k_ln<1><<<4096, 256>>>(n1g, n1b, shift);
        k_gemm<0, float ><<<dim3(6, 256), 128>>>(p_win, wbase,          qkvb,  p_qkv, 768, 256, 0);
        k_attn<<<4096, 64>>>(rpb, shift);
        k_gemm<2, float ><<<dim3(2, 256), 128>>>(p_att, wbase + 196608, projb, (float*)nullptr, 256, 256, shift);
        k_ln<0><<<4096, 256>>>(n2g, n2b, 0);
        k_gemm<1, __half><<<dim3(8, 256), 128>>>(p_win, wbase + 262144, fc1b,  p_mlp, 1024, 256, 0);
        k_gemm<3, float ><<<dim3(2, 256), 128>>>(p_mlp, wbase + 524288, fc2b,  (float*)nullptr, 256, 1024, 0);
    }

    k_final<<<1024, 256>>>(norm_g, norm_b, out);
}

// round 6
// speedup vs baseline: 3.5212x; 1.2435x over previous
#include <cuda_runtime.h>
#include <cuda_fp16.h>
#include <math.h>

#define L_TOK 32768

// ---------------- scratch (device globals; no runtime allocation) ----------------
__device__ float  g_x  [L_TOK * 256];   // residual stream (fp32)
__device__ __half g_win[L_TOK * 256];   // LN output / partitioned windows (fp16)
__device__ __half g_qkv[L_TOK * 768];   // qkv (fp16)
__device__ __half g_att[L_TOK * 256];   // attention out (fp16, window layout)
__device__ __half g_mlp[L_TOK * 1024];  // MLP hidden (fp16)
__device__ __half g_wbuf[2 * 786432];   // fp16 weights

__device__ __forceinline__ int win_to_tok(int r, int shift) {
    int w = r >> 6, n = r & 63;
    int h  = ((w >> 6) << 2)        + (n >> 4);
    int wy = (((w >> 3) & 7) << 2)  + ((n >> 2) & 3);
    int t  = ((w & 7) << 2)         + (n & 3);
    h  = (h  + shift) & 31;
    wy = (wy + shift) & 31;
    t  = (t  + shift) & 31;
    return (h << 10) + (wy << 5) + t;
}

__device__ __forceinline__ void cp16(void* s, const void* g) {
    unsigned sa = (unsigned)__cvta_generic_to_shared(s);
    asm volatile("cp.async.cg.shared.global [%0], [%1], 16;\n" :: "r"(sa), "l"(g));
}
__device__ __forceinline__ unsigned smem_u32(const void* p) {
    unsigned a;
    asm("{ .reg .u64 t; cvta.to.shared.u64 t, %1; cvt.u32.u64 %0, t; }" : "=r"(a) : "l"(p));
    return a;
}
__device__ __forceinline__ void mma_f16(float* d, const unsigned* a, const unsigned* b) {
    asm volatile(
        "mma.sync.aligned.m16n8k16.row.col.f32.f16.f16.f32 "
        "{%0,%1,%2,%3}, {%4,%5,%6,%7}, {%8,%9}, {%0,%1,%2,%3};\n"
        : "+f"(d[0]), "+f"(d[1]), "+f"(d[2]), "+f"(d[3])
        : "r"(a[0]), "r"(a[1]), "r"(a[2]), "r"(a[3]), "r"(b[0]), "r"(b[1]));
}
__device__ __forceinline__ void ldsm4(unsigned* r, unsigned addr) {
    asm volatile("ldmatrix.sync.aligned.m8n8.x4.shared.b16 {%0,%1,%2,%3}, [%4];"
        : "=r"(r[0]), "=r"(r[1]), "=r"(r[2]), "=r"(r[3]) : "r"(addr));
}
__device__ __forceinline__ void ldsm2(unsigned* r, unsigned addr) {
    asm volatile("ldmatrix.sync.aligned.m8n8.x2.shared.b16 {%0,%1}, [%2];"
        : "=r"(r[0]), "=r"(r[1]) : "r"(addr));
}
__device__ __forceinline__ unsigned packh2(float a, float b) {
    __half2 h = __floats2half2_rn(a, b);
    return *(unsigned*)&h;
}

// ---------------- residual init ----------------
__global__ void k_copy(const float* __restrict__ src) {
    int i = blockIdx.x * 256 + threadIdx.x;
    ((float4*)g_x)[i] = ((const float4*)src)[i];
}

// ---------------- fp16 weight conversion (all 8 weight tensors, one launch) ----------------
__global__ void k_roundall(const float* s0, const float* s1, const float* s2, const float* s3,
                           const float* s4, const float* s5, const float* s6, const float* s7) {
    int i = blockIdx.x * 256 + threadIdx.x;            // 0 .. 393215 (float4 units)
    int set = i >= 196608;
    int j = set ? i - 196608 : i;
    const float* src;
    int dstoff;
    if      (j <  49152) { src = set ? s4 : s0; dstoff = j; }
    else if (j <  65536) { src = set ? s5 : s1; dstoff = (196608 >> 2) + (j - 49152); }
    else if (j < 131072) { src = set ? s6 : s2; dstoff = (262144 >> 2) + (j - 65536); }
    else                 { src = set ? s7 : s3; dstoff = (524288 >> 2) + (j - 131072); }
    int local = (j < 49152) ? j : (j < 65536) ? j - 49152 : (j < 131072) ? j - 65536 : j - 131072;
    float4 v = ((const float4*)src)[local];
    uint2 o;
    o.x = packh2(v.x, v.y);
    o.y = packh2(v.z, v.w);
    ((uint2*)(g_wbuf + set * 786432))[dstoff] = o;
}

// ---------------- LayerNorm (REMAP=1: fused shift+partition gather); fp16 out ----------------
template<int REMAP>
__global__ __launch_bounds__(256) void k_ln(const float* __restrict__ gam,
                                            const float* __restrict__ bet, int shift) {
    int warp = threadIdx.x >> 5, lane = threadIdx.x & 31;
    int r = (blockIdx.x << 3) + warp;
    int src = REMAP ? win_to_tok(r, shift) : r;
    const float4* xp = (const float4*)(g_x + src * 256);
    float4 a = xp[lane * 2], c = xp[lane * 2 + 1];
    float s  = a.x + a.y + a.z + a.w + c.x + c.y + c.z + c.w;
    float sq = a.x*a.x + a.y*a.y + a.z*a.z + a.w*a.w
             + c.x*c.x + c.y*c.y + c.z*c.z + c.w*c.w;
    #pragma unroll
    for (int o = 16; o; o >>= 1) {
        s  += __shfl_xor_sync(0xffffffffu, s, o);
        sq += __shfl_xor_sync(0xffffffffu, sq, o);
    }
    float mean = s * (1.0f / 256.0f);
    float inv = rsqrtf(sq * (1.0f / 256.0f) - mean * mean + 1e-5f);
    float4 g0 = ((const float4*)gam)[lane*2], g1 = ((const float4*)gam)[lane*2+1];
    float4 b0 = ((const float4*)bet)[lane*2], b1 = ((const float4*)bet)[lane*2+1];
    uint4 o;
    o.x = packh2((a.x-mean)*inv*g0.x + b0.x, (a.y-mean)*inv*g0.y + b0.y);
    o.y = packh2((a.z-mean)*inv*g0.z + b0.z, (a.w-mean)*inv*g0.w + b0.w);
    o.z = packh2((c.x-mean)*inv*g1.x + b1.x, (c.y-mean)*inv*g1.y + b1.y);
    o.w = packh2((c.z-mean)*inv*g1.z + b1.z, (c.w-mean)*inv*g1.w + b1.w);
    ((uint4*)(g_win + r * 256))[lane] = o;
}

// ---------------- tensor-core windowed attention ----------------
// block = (window, head-pair); 4 warps: warps {0,1}->head hp*2 (m 0-31 / 32-63),
// warps {2,3}->head hp*2+1. Per warp: m32 n64 k32 QK, fragment softmax, m32 n32 k64 PV.
#define AT_STR 72   // smem row stride in halves (144B: conflict-free LDSM)
__global__ __launch_bounds__(128) void k_attn_tc(const float* __restrict__ rpb, int shift) {
    int w  = blockIdx.x >> 2;
    int hp = blockIdx.x & 3;
    __shared__ __half sq[64 * AT_STR];
    __shared__ __half sk[64 * AT_STR];
    __shared__ __half sv[64 * AT_STR];   // transposed: row = dim (2 heads x 32), col = token
    __shared__ float  srpb[686];
    __shared__ int    slab[64];

    const int tid = threadIdx.x;
    const int lane = tid & 31, wid = tid >> 5;

    // stage q, k (layout [tok][64] for the head pair) via cp.async
    #pragma unroll
    for (int j = 0; j < 4; j++) {
        int c = tid + j * 128;                 // 512 chunks of 16B
        int tok = c >> 3, cg = c & 7;
        const __half* base = g_qkv + (size_t)(w * 64 + tok) * 768 + hp * 64 + cg * 8;
        cp16(&sq[tok * AT_STR + cg * 8], base);
        cp16(&sk[tok * AT_STR + cg * 8], base + 256);
    }
    asm volatile("cp.async.commit_group;\n" ::: "memory");
    // stage v transposed: sv[dim][tok]
    #pragma unroll
    for (int j = 0; j < 16; j++) {
        int e = tid + j * 128;                 // 2048 half2 elements
        int tok = e >> 5, dp = e & 31;
        __half2 v = *(const __half2*)(g_qkv + (size_t)(w * 64 + tok) * 768 + 512 + hp * 64 + dp * 2);
        sv[(dp * 2 + 0) * AT_STR + tok] = __low2half(v);
        sv[(dp * 2 + 1) * AT_STR + tok] = __high2half(v);
    }
    // rel-pos bias for both heads + region labels
    for (int i = tid; i < 686; i += 128)
        srpb[i] = rpb[(i % 343) * 8 + hp * 2 + (i / 343)];
    if (tid < 64) {
        int n = tid;
        int gh = ((w >> 6) << 2)       + (n >> 4);
        int gw = (((w >> 3) & 7) << 2) + ((n >> 2) & 3);
        int gt = ((w & 7) << 2)        + (n & 3);
        int rh = (gh < 28) ? 0 : ((gh < 30) ? 1 : 2);
        int rw = (gw < 28) ? 0 : ((gw < 30) ? 1 : 2);
        int rt = (gt < 28) ? 0 : ((gt < 30) ? 1 : 2);
        slab[n] = rh * 9 + rw * 3 + rt;
    }
    asm volatile("cp.async.wait_group 0;\n" ::: "memory");
    __syncthreads();

    const int hsel  = wid >> 1;                // head within pair
    const int mbase = (wid & 1) * 32;          // query-row offset
    const int h     = hp * 2 + hsel;
    const int hoff  = hsel * 32;               // column offset in sq/sk, row offset in sv

    // ---- QK^T : m32 n64 k32 ----
    float acc[2][8][4];
    #pragma unroll
    for (int mt = 0; mt < 2; mt++)
        #pragma unroll
        for (int nt = 0; nt < 8; nt++)
            #pragma unroll
            for (int r = 0; r < 4; r++) acc[mt][nt][r] = 0.f;

    #pragma unroll
    for (int kc = 0; kc < 2; kc++) {
        unsigned a[2][4];
        #pragma unroll
        for (int mt = 0; mt < 2; mt++) {
            int t = lane >> 3;
            int row = mbase + mt * 16 + (t & 1) * 8 + (lane & 7);
            int col = hoff + kc * 16 + (t >> 1) * 8;
            ldsm4(a[mt], smem_u32(&sq[row * AT_STR + col]));
        }
        #pragma unroll
        for (int nt = 0; nt < 8; nt++) {
            unsigned b[2];
            int row = nt * 8 + (lane & 7);
            int col = hoff + kc * 16 + ((lane >> 3) & 1) * 8;
            ldsm2(b, smem_u32(&sk[row * AT_STR + col]));
            #pragma unroll
            for (int mt = 0; mt < 2; mt++) mma_f16(acc[mt][nt], a[mt], b);
        }
    }

    // ---- scale + rpb + mask on fragments ----
    int rh4[4], rw4[4], rt4[4], rlab[4];
    #pragma unroll
    for (int i = 0; i < 4; i++) {
        int tok = mbase + (i >> 1) * 16 + (i & 1) * 8 + (lane >> 2);
        rh4[i] = tok >> 4; rw4[i] = (tok >> 2) & 3; rt4[i] = tok & 3;
        rlab[i] = slab[tok];
    }
    #pragma unroll
    for (int mt = 0; mt < 2; mt++)
        #pragma unroll
        for (int nt = 0; nt < 8; nt++)
            #pragma unroll
            for (int r = 0; r < 4; r++) {
                int i  = mt * 2 + (r >> 1);
                int cn = nt * 8 + ((lane & 3) << 1) + (r & 1);
                int idx = ((rh4[i] - (cn >> 4) + 3) * 7 + (rw4[i] - ((cn >> 2) & 3) + 3)) * 7
                        + (rt4[i] - (cn & 3) + 3);
                float s = acc[mt][nt][r] * 0.17677669529663687f + srpb[hsel * 343 + idx];
                if (shift && rlab[i] != slab[cn]) s -= 100.f;
                acc[mt][nt][r] = s;
            }

    // ---- fragment softmax (rows shared by lane quads) ----
    float mx[4] = {-1e30f, -1e30f, -1e30f, -1e30f};
    #pragma unroll
    for (int mt = 0; mt < 2; mt++)
        #pragma unroll
        for (int nt = 0; nt < 8; nt++)
            #pragma unroll
            for (int r = 0; r < 4; r++)
                mx[mt * 2 + (r >> 1)] = fmaxf(mx[mt * 2 + (r >> 1)], acc[mt][nt][r]);
    #pragma unroll
    for (int i = 0; i < 4; i++) {
        mx[i] = fmaxf(mx[i], __shfl_xor_sync(0xffffffffu, mx[i], 1));
        mx[i] = fmaxf(mx[i], __shfl_xor_sync(0xffffffffu, mx[i], 2));
    }
    float sm[4] = {0.f, 0.f, 0.f, 0.f};
    #pragma unroll
    for (int mt = 0; mt < 2; mt++)
        #pragma unroll
        for (int nt = 0; nt < 8; nt++)
            #pragma unroll
            for (int r = 0; r < 4; r++) {
                float p = __expf(acc[mt][nt][r] - mx[mt * 2 + (r >> 1)]);
                acc[mt][nt][r] = p;
                sm[mt * 2 + (r >> 1)] += p;
            }
    #pragma unroll
    for (int i = 0; i < 4; i++) {
        sm[i] += __shfl_xor_sync(0xffffffffu, sm[i], 1);
        sm[i] += __shfl_xor_sync(0xffffffffu, sm[i], 2);
    }

    // ---- P x V : m32 n32 k64 (P fragments reused as A operands) ----
    float acc2[2][4][4];
    #pragma unroll
    for (int mt = 0; mt < 2; mt++)
        #pragma unroll
        for (int nt = 0; nt < 4; nt++)
            #pragma unroll
            for (int r = 0; r < 4; r++) acc2[mt][nt][r] = 0.f;

    #pragma unroll
    for (int kc = 0; kc < 4; kc++) {
        unsigned ah[2][4];
        #pragma unroll
        for (int mt = 0; mt < 2; mt++) {
            ah[mt][0] = packh2(acc[mt][2*kc  ][0], acc[mt][2*kc  ][1]);
            ah[mt][1] = packh2(acc[mt][2*kc  ][2], acc[mt][2*kc  ][3]);
            ah[mt][2] = packh2(acc[mt][2*kc+1][0], acc[mt][2*kc+1][1]);
            ah[mt][3] = packh2(acc[mt][2*kc+1][2], acc[mt][2*kc+1][3]);
        }
        #pragma unroll
        for (int nt = 0; nt < 4; nt++) {
            unsigned b[2];
            int row = hoff + nt * 8 + (lane & 7);
            int col = kc * 16 + ((lane >> 3) & 1) * 8;
            ldsm2(b, smem_u32(&sv[row * AT_STR + col]));
            #pragma unroll
            for (int mt = 0; mt < 2; mt++) mma_f16(acc2[mt][nt], ah[mt], b);
        }
    }

    // ---- normalize + store fp16 ----
    #pragma unroll
    for (int mt = 0; mt < 2; mt++)
        #pragma unroll
        for (int hf = 0; hf < 2; hf++) {
            float inv = 1.f / sm[mt * 2 + hf];
            int tok = mbase + mt * 16 + hf * 8 + (lane >> 2);
            __half* op = g_att + (size_t)(w * 64 + tok) * 256 + h * 32 + ((lane & 3) << 1);
            #pragma unroll
            for (int nt = 0; nt < 4; nt++) {
                unsigned hv = packh2(acc2[mt][nt][hf * 2] * inv, acc2[mt][nt][hf * 2 + 1] * inv);
                *(unsigned*)(op + nt * 8) = hv;
            }
        }
}

// ---------------- fp16 tensor-core NT GEMM: C[M,N] = A[M,K]*B[N,K]^T + bias ----------------
// EPI 0: +bias store fp16  1: +bias GELU store fp16  2: scatter-add residual  3: add residual
template<int EPI, typename OutT>
__global__ __launch_bounds__(128, 2) void k_gemm(const __half* __restrict__ A,
                                                 const __half* __restrict__ B,
                                                 const float* __restrict__ bias,
                                                 OutT* __restrict__ Cout,
                                                 int N, int K, int shift) {
    __shared__ unsigned As[3][2048];
    __shared__ unsigned Bs[3][2048];
    const int t = threadIdx.x;
    const int lane = t & 31, wid = t >> 5;
    const int warp_m = wid & 1, warp_n = wid >> 1;
    const int rowBase = blockIdx.y << 7;
    const int colBase = blockIdx.x << 7;

    float acc[4][8][4];
    #pragma unroll
    for (int mt = 0; mt < 4; mt++)
        #pragma unroll
        for (int nt = 0; nt < 8; nt++)
            #pragma unroll
            for (int r = 0; r < 4; r++) acc[mt][nt][r] = 0.f;

    auto load_tile = [&](int buf, int k0) {
        #pragma unroll
        for (int j = 0; j < 4; j++) {
            int q = t + j * 128;
            int r = q >> 2, cg = q & 3;
            int ks = cg >> 1, reg = ((r >> 3) & 1) | ((cg & 1) << 1);
            int off = (((r >> 4) * 2 + ks) * 4 + reg) * 32 + (r & 7) * 4;
            cp16(&As[buf][off], A + (size_t)(rowBase + r) * K + k0 + cg * 8);
        }
        #pragma unroll
        for (int j = 0; j < 4; j++) {
            int q = t + j * 128;
            int n = q >> 2, cg = q & 3;
            int ks = cg >> 1, reg = cg & 1;
            int off = (((n >> 3) * 2 + ks) * 2 + reg) * 32 + (n & 7) * 4;
            cp16(&Bs[buf][off], B + (size_t)(colBase + n) * K + k0 + cg * 8);
        }
        asm volatile("cp.async.commit_group;\n" ::: "memory");
    };

    const int ntiles = K >> 5;
    load_tile(0, 0);
    load_tile(1, 32);
    for (int i = 0; i < ntiles; i++) {
        asm volatile("cp.async.wait_group 1;\n" ::: "memory");
        __syncthreads();
        if (i + 2 < ntiles) load_tile((i + 2) % 3, (i + 2) << 5);
        const int buf = i % 3;
        #pragma unroll
        for (int ks = 0; ks < 2; ks++) {
            unsigned af[4][4], bf[8][2];
            #pragma unroll
            for (int mt = 0; mt < 4; mt++) {
                int base = (((warp_m * 4 + mt) * 2 + ks) * 4) * 32 + lane;
                #pragma unroll
                for (int r = 0; r < 4; r++) af[mt][r] = As[buf][base + r * 32];
            }
            #pragma unroll
            for (int nt = 0; nt < 8; nt++) {
                int base = (((warp_n * 8 + nt) * 2 + ks) * 2) * 32 + lane;
                #pragma unroll
                for (int r = 0; r < 2; r++) bf[nt][r] = Bs[buf][base + r * 32];
            }
            #pragma unroll
            for (int mt = 0; mt < 4; mt++)
                #pragma unroll
                for (int nt = 0; nt < 8; nt++)
                    mma_f16(acc[mt][nt], af[mt], bf[nt]);
        }
        __syncthreads();
    }

    float2 bv[8];
    #pragma unroll
    for (int nt = 0; nt < 8; nt++)
        bv[nt] = *(const float2*)(bias + colBase + warp_n * 64 + nt * 8 + (lane & 3) * 2);

    #pragma unroll
    for (int mt = 0; mt < 4; mt++) {
        #pragma unroll
        for (int i = 0; i < 2; i++) {
            int row = rowBase + warp_m * 64 + mt * 16 + (lane >> 2) + i * 8;
            int dst = (EPI == 2) ? win_to_tok(row, shift) : row;
            #pragma unroll
            for (int nt = 0; nt < 8; nt++) {
                int col = colBase + warp_n * 64 + nt * 8 + (lane & 3) * 2;
                float v0 = acc[mt][nt][i * 2 + 0] + bv[nt].x;
                float v1 = acc[mt][nt][i * 2 + 1] + bv[nt].y;
                if (EPI == 0) {
                    *(unsigned*)((__half*)Cout + (size_t)row * N + col) = packh2(v0, v1);
                } else if (EPI == 1) {
                    v0 = 0.5f * v0 * (1.0f + erff(v0 * 0.70710678118654752f));
                    v1 = 0.5f * v1 * (1.0f + erff(v1 * 0.70710678118654752f));
                    *(unsigned*)((__half*)Cout + (size_t)row * N + col) = packh2(v0, v1);
                } else {
                    float2* rp = (float2*)(g_x + dst * 256 + col);
                    float2 r0 = *rp;
                    r0.x += v0; r0.y += v1;
                    *rp = r0;
                }
            }
        }
    }
}

// ---------------- final LN + [L,C] -> [C,L] transpose ----------------
__global__ __launch_bounds__(256) void k_final(const float* __restrict__ gam,
                                               const float* __restrict__ bet,
                                               float* __restrict__ out) {
    __shared__ float sm[256][33];
    int warp = threadIdx.x >> 5, lane = threadIdx.x & 31;
    int l0 = blockIdx.x << 5;
    float4 g0 = ((const float4*)gam)[lane*2], g1 = ((const float4*)gam)[lane*2+1];
    float4 b0 = ((const float4*)bet)[lane*2], b1 = ((const float4*)bet)[lane*2+1];
    #pragma unroll
    for (int i = 0; i < 4; i++) {
        int tok = (warp << 2) + i;
        const float4* xp = (const float4*)(g_x + (l0 + tok) * 256);
        float4 a = xp[lane*2], c = xp[lane*2+1];
        float s  = a.x + a.y + a.z + a.w + c.x + c.y + c.z + c.w;
        float sq = a.x*a.x + a.y*a.y + a.z*a.z + a.w*a.w
                 + c.x*c.x + c.y*c.y + c.z*c.z + c.w*c.w;
        #pragma unroll
        for (int o = 16; o; o >>= 1) {
            s  += __shfl_xor_sync(0xffffffffu, s, o);
            sq += __shfl_xor_sync(0xffffffffu, sq, o);
        }
        float mean = s * (1.0f / 256.0f);
        float inv = rsqrtf(sq * (1.0f / 256.0f) - mean * mean + 1e-5f);
        int cb = lane * 8;
        sm[cb+0][tok] = (a.x-mean)*inv*g0.x + b0.x;
        sm[cb+1][tok] = (a.y-mean)*inv*g0.y + b0.y;
        sm[cb+2][tok] = (a.z-mean)*inv*g0.z + b0.z;
        sm[cb+3][tok] = (a.w-mean)*inv*g0.w + b0.w;
        sm[cb+4][tok] = (c.x-mean)*inv*g1.x + b1.x;
        sm[cb+5][tok] = (c.y-mean)*inv*g1.y + b1.y;
        sm[cb+6][tok] = (c.z-mean)*inv*g1.z + b1.z;
        sm[cb+7][tok] = (c.w-mean)*inv*g1.w + b1.w;
    }
    __syncthreads();
    int lt = threadIdx.x & 31;
    int cw = threadIdx.x >> 5;
    #pragma unroll
    for (int cc = 0; cc < 32; cc++) {
        int c = (cc << 3) + cw;
        out[c * L_TOK + l0 + lt] = sm[c][lt];
    }
}

// ---------------- launch ----------------
extern "C" void kernel_launch(void* const* d_in, const int* in_sizes, int n_in,
                              void* d_out, int out_size) {
    const float* x      = (const float*)d_in[0];
    const float* norm_g = (const float*)d_in[4];
    const float* norm_b = (const float*)d_in[5];
    float* out = (float*)d_out;

    __half *p_win, *p_qkv, *p_att, *p_mlp, *p_w;
    cudaGetSymbolAddress((void**)&p_win, g_win);
    cudaGetSymbolAddress((void**)&p_qkv, g_qkv);
    cudaGetSymbolAddress((void**)&p_att, g_att);
    cudaGetSymbolAddress((void**)&p_mlp, g_mlp);
    cudaGetSymbolAddress((void**)&p_w,   g_wbuf);

    k_copy<<<8192, 256>>>(x);
    k_roundall<<<1536, 256>>>((const float*)d_in[8],  (const float*)d_in[11],
                              (const float*)d_in[15], (const float*)d_in[17],
                              (const float*)d_in[21], (const float*)d_in[24],
                              (const float*)d_in[28], (const float*)d_in[30]);

    for (int blk = 0; blk < 2; blk++) {
        int o = 6 + blk * 13;
        int shift = blk ? 2 : 0;
        const float* n1g   = (const float*)d_in[o+0];
        const float* n1b   = (const float*)d_in[o+1];
        const float* qkvb  = (const float*)d_in[o+3];
        const float* rpb   = (const float*)d_in[o+4];
        const float* projb = (const float*)d_in[o+6];
        const float* n2g   = (const float*)d_in[o+7];
        const float* n2b   = (const float*)d_in[o+8];
        const float* fc1b  = (const float*)d_in[o+10];
        const float* fc2b  = (const float*)d_in[o+12];
        __half* wbase = p_w + blk * 786432;

        k_ln<1><<<4096, 256>>>(n1g, n1b, shift);
        k_gemm<0, __half><<<dim3(6, 256), 128>>>(p_win, wbase,          qkvb,  p_qkv, 768, 256, 0);
        k_attn_tc<<<2048, 128>>>(rpb, shift);
        k_gemm<2, float ><<<dim3(2, 256), 128>>>(p_att, wbase + 196608, projb, (float*)nullptr, 256, 256, shift);
        k_ln<0><<<4096, 256>>>(n2g, n2b, 0);
        k_gemm<1, __half><<<dim3(8, 256), 128>>>(p_win, wbase + 262144, fc1b,  p_mlp, 1024, 256, 0);
        k_gemm<3, float ><<<dim3(2, 256), 128>>>(p_mlp, wbase + 524288, fc2b,  (float*)nullptr, 256, 1024, 0);
    }

    k_final<<<1024, 256>>>(norm_g, norm_b, out);
}

// round 8
// speedup vs baseline: 5.2468x; 1.4900x over previous
#include <cuda_runtime.h>
#include <cuda_fp16.h>
#include <math.h>

#define L_TOK 32768

// ---------------- scratch (device globals; no runtime allocation) ----------------
__device__ float  g_x  [L_TOK * 256];   // residual stream (fp32)
__device__ __half g_win[L_TOK * 256];   // LN output / partitioned windows (fp16)
__device__ __half g_qkv[L_TOK * 768];   // qkv (fp16)
__device__ __half g_att[L_TOK * 256];   // attention out (fp16, window layout)
__device__ __half g_mlp[L_TOK * 1024];  // MLP hidden (fp16)
__device__ __half g_wbuf[2 * 786432];   // fp16 weights

__device__ __forceinline__ int win_to_tok(int r, int shift) {
    int w = r >> 6, n = r & 63;
    int h  = ((w >> 6) << 2)        + (n >> 4);
    int wy = (((w >> 3) & 7) << 2)  + ((n >> 2) & 3);
    int t  = ((w & 7) << 2)         + (n & 3);
    h  = (h  + shift) & 31;
    wy = (wy + shift) & 31;
    t  = (t  + shift) & 31;
    return (h << 10) + (wy << 5) + t;
}

__device__ __forceinline__ void cp16(void* s, const void* g) {
    unsigned sa = (unsigned)__cvta_generic_to_shared(s);
    asm volatile("cp.async.cg.shared.global [%0], [%1], 16;\n" :: "r"(sa), "l"(g));
}
__device__ __forceinline__ unsigned smem_u32(const void* p) {
    unsigned a;
    asm("{ .reg .u64 t; cvta.to.shared.u64 t, %1; cvt.u32.u64 %0, t; }" : "=r"(a) : "l"(p));
    return a;
}
__device__ __forceinline__ void mma_f16(float* d, const unsigned* a, const unsigned* b) {
    asm volatile(
        "mma.sync.aligned.m16n8k16.row.col.f32.f16.f16.f32 "
        "{%0,%1,%2,%3}, {%4,%5,%6,%7}, {%8,%9}, {%0,%1,%2,%3};\n"
        : "+f"(d[0]), "+f"(d[1]), "+f"(d[2]), "+f"(d[3])
        : "r"(a[0]), "r"(a[1]), "r"(a[2]), "r"(a[3]), "r"(b[0]), "r"(b[1]));
}
__device__ __forceinline__ void ldsm4(unsigned* r, unsigned addr) {
    asm volatile("ldmatrix.sync.aligned.m8n8.x4.shared.b16 {%0,%1,%2,%3}, [%4];"
        : "=r"(r[0]), "=r"(r[1]), "=r"(r[2]), "=r"(r[3]) : "r"(addr));
}
__device__ __forceinline__ void ldsm2(unsigned* r, unsigned addr) {
    asm volatile("ldmatrix.sync.aligned.m8n8.x2.shared.b16 {%0,%1}, [%2];"
        : "=r"(r[0]), "=r"(r[1]) : "r"(addr));
}
__device__ __forceinline__ unsigned packh2(float a, float b) {
    __half2 h = __floats2half2_rn(a, b);
    return *(unsigned*)&h;
}

// ---------------- residual init ----------------
__global__ void k_copy(const float* __restrict__ src) {
    int i = blockIdx.x * 256 + threadIdx.x;
    ((float4*)g_x)[i] = ((const float4*)src)[i];
}

// ---------------- fp16 weight conversion (all 8 weight tensors, one launch) ----------------
__global__ void k_roundall(const float* s0, const float* s1, const float* s2, const float* s3,
                           const float* s4, const float* s5, const float* s6, const float* s7) {
    int i = blockIdx.x * 256 + threadIdx.x;            // 0 .. 393215 (float4 units)
    int set = i >= 196608;
    int j = set ? i - 196608 : i;
    const float* src;
    int dstoff;
    if      (j <  49152) { src = set ? s4 : s0; dstoff = j; }
    else if (j <  65536) { src = set ? s5 : s1; dstoff = (196608 >> 2) + (j - 49152); }
    else if (j < 131072) { src = set ? s6 : s2; dstoff = (262144 >> 2) + (j - 65536); }
    else                 { src = set ? s7 : s3; dstoff = (524288 >> 2) + (j - 131072); }
    int local = (j < 49152) ? j : (j < 65536) ? j - 49152 : (j < 131072) ? j - 65536 : j - 131072;
    float4 v = ((const float4*)src)[local];
    uint2 o;
    o.x = packh2(v.x, v.y);
    o.y = packh2(v.z, v.w);
    ((uint2*)(g_wbuf + set * 786432))[dstoff] = o;
}

// ---------------- LayerNorm (REMAP=1: fused shift+partition gather); fp16 out ----------------
template<int REMAP>
__global__ __launch_bounds__(256) void k_ln(const float* __restrict__ gam,
                                            const float* __restrict__ bet, int shift) {
    int warp = threadIdx.x >> 5, lane = threadIdx.x & 31;
    int r = (blockIdx.x << 3) + warp;
    int src = REMAP ? win_to_tok(r, shift) : r;
    const float4* xp = (const float4*)(g_x + src * 256);
    float4 a = xp[lane * 2], c = xp[lane * 2 + 1];
    float s  = a.x + a.y + a.z + a.w + c.x + c.y + c.z + c.w;
    float sq = a.x*a.x + a.y*a.y + a.z*a.z + a.w*a.w
             + c.x*c.x + c.y*c.y + c.z*c.z + c.w*c.w;
    #pragma unroll
    for (int o = 16; o; o >>= 1) {
        s  += __shfl_xor_sync(0xffffffffu, s, o);
        sq += __shfl_xor_sync(0xffffffffu, sq, o);
    }
    float mean = s * (1.0f / 256.0f);
    float inv = rsqrtf(sq * (1.0f / 256.0f) - mean * mean + 1e-5f);
    float4 g0 = ((const float4*)gam)[lane*2], g1 = ((const float4*)gam)[lane*2+1];
    float4 b0 = ((const float4*)bet)[lane*2], b1 = ((const float4*)bet)[lane*2+1];
    uint4 o;
    o.x = packh2((a.x-mean)*inv*g0.x + b0.x, (a.y-mean)*inv*g0.y + b0.y);
    o.y = packh2((a.z-mean)*inv*g0.z + b0.z, (a.w-mean)*inv*g0.w + b0.w);
    o.z = packh2((c.x-mean)*inv*g1.x + b1.x, (c.y-mean)*inv*g1.y + b1.y);
    o.w = packh2((c.z-mean)*inv*g1.z + b1.z, (c.w-mean)*inv*g1.w + b1.w);
    ((uint4*)(g_win + r * 256))[lane] = o;
}

// ---------------- tensor-core windowed attention ----------------
#define AT_STR 72
__global__ __launch_bounds__(128) void k_attn_tc(const float* __restrict__ rpb, int shift) {
    int w  = blockIdx.x >> 2;
    int hp = blockIdx.x & 3;
    __shared__ __half sq[64 * AT_STR];
    __shared__ __half sk[64 * AT_STR];
    __shared__ __half sv[64 * AT_STR];
    __shared__ float  srpb[686];
    __shared__ int    slab[64];

    const int tid = threadIdx.x;
    const int lane = tid & 31, wid = tid >> 5;

    #pragma unroll
    for (int j = 0; j < 4; j++) {
        int c = tid + j * 128;
        int tok = c >> 3, cg = c & 7;
        const __half* base = g_qkv + (size_t)(w * 64 + tok) * 768 + hp * 64 + cg * 8;
        cp16(&sq[tok * AT_STR + cg * 8], base);
        cp16(&sk[tok * AT_STR + cg * 8], base + 256);
    }
    asm volatile("cp.async.commit_group;\n" ::: "memory");
    #pragma unroll
    for (int j = 0; j < 16; j++) {
        int e = tid + j * 128;
        int tok = e >> 5, dp = e & 31;
        __half2 v = *(const __half2*)(g_qkv + (size_t)(w * 64 + tok) * 768 + 512 + hp * 64 + dp * 2);
        sv[(dp * 2 + 0) * AT_STR + tok] = __low2half(v);
        sv[(dp * 2 + 1) * AT_STR + tok] = __high2half(v);
    }
    for (int i = tid; i < 686; i += 128)
        srpb[i] = rpb[(i % 343) * 8 + hp * 2 + (i / 343)];
    if (tid < 64) {
        int n = tid;
        int gh = ((w >> 6) << 2)       + (n >> 4);
        int gw = (((w >> 3) & 7) << 2) + ((n >> 2) & 3);
        int gt = ((w & 7) << 2)        + (n & 3);
        int rh = (gh < 28) ? 0 : ((gh < 30) ? 1 : 2);
        int rw = (gw < 28) ? 0 : ((gw < 30) ? 1 : 2);
        int rt = (gt < 28) ? 0 : ((gt < 30) ? 1 : 2);
        slab[n] = rh * 9 + rw * 3 + rt;
    }
    asm volatile("cp.async.wait_group 0;\n" ::: "memory");
    __syncthreads();

    const int hsel  = wid >> 1;
    const int mbase = (wid & 1) * 32;
    const int h     = hp * 2 + hsel;
    const int hoff  = hsel * 32;

    float acc[2][8][4];
    #pragma unroll
    for (int mt = 0; mt < 2; mt++)
        #pragma unroll
        for (int nt = 0; nt < 8; nt++)
            #pragma unroll
            for (int r = 0; r < 4; r++) acc[mt][nt][r] = 0.f;

    #pragma unroll
    for (int kc = 0; kc < 2; kc++) {
        unsigned a[2][4];
        #pragma unroll
        for (int mt = 0; mt < 2; mt++) {
            int t = lane >> 3;
            int row = mbase + mt * 16 + (t & 1) * 8 + (lane & 7);
            int col = hoff + kc * 16 + (t >> 1) * 8;
            ldsm4(a[mt], smem_u32(&sq[row * AT_STR + col]));
        }
        #pragma unroll
        for (int nt = 0; nt < 8; nt++) {
            unsigned b[2];
            int row = nt * 8 + (lane & 7);
            int col = hoff + kc * 16 + ((lane >> 3) & 1) * 8;
            ldsm2(b, smem_u32(&sk[row * AT_STR + col]));
            #pragma unroll
            for (int mt = 0; mt < 2; mt++) mma_f16(acc[mt][nt], a[mt], b);
        }
    }

    int rh4[4], rw4[4], rt4[4], rlab[4];
    #pragma unroll
    for (int i = 0; i < 4; i++) {
        int tok = mbase + (i >> 1) * 16 + (i & 1) * 8 + (lane >> 2);
        rh4[i] = tok >> 4; rw4[i] = (tok >> 2) & 3; rt4[i] = tok & 3;
        rlab[i] = slab[tok];
    }
    #pragma unroll
    for (int mt = 0; mt < 2; mt++)
        #pragma unroll
        for (int nt = 0; nt < 8; nt++)
            #pragma unroll
            for (int r = 0; r < 4; r++) {
                int i  = mt * 2 + (r >> 1);
                int cn = nt * 8 + ((lane & 3) << 1) + (r & 1);
                int idx = ((rh4[i] - (cn >> 4) + 3) * 7 + (rw4[i] - ((cn >> 2) & 3) + 3)) * 7
                        + (rt4[i] - (cn & 3) + 3);
                float s = acc[mt][nt][r] * 0.17677669529663687f + srpb[hsel * 343 + idx];
                if (shift && rlab[i] != slab[cn]) s -= 100.f;
                acc[mt][nt][r] = s;
            }

    float mx[4] = {-1e30f, -1e30f, -1e30f, -1e30f};
    #pragma unroll
    for (int mt = 0; mt < 2; mt++)
        #pragma unroll
        for (int nt = 0; nt < 8; nt++)
            #pragma unroll
            for (int r = 0; r < 4; r++)
                mx[mt * 2 + (r >> 1)] = fmaxf(mx[mt * 2 + (r >> 1)], acc[mt][nt][r]);
    #pragma unroll
    for (int i = 0; i < 4; i++) {
        mx[i] = fmaxf(mx[i], __shfl_xor_sync(0xffffffffu, mx[i], 1));
        mx[i] = fmaxf(mx[i], __shfl_xor_sync(0xffffffffu, mx[i], 2));
    }
    float sm[4] = {0.f, 0.f, 0.f, 0.f};
    #pragma unroll
    for (int mt = 0; mt < 2; mt++)
        #pragma unroll
        for (int nt = 0; nt < 8; nt++)
            #pragma unroll
            for (int r = 0; r < 4; r++) {
                float p = __expf(acc[mt][nt][r] - mx[mt * 2 + (r >> 1)]);
                acc[mt][nt][r] = p;
                sm[mt * 2 + (r >> 1)] += p;
            }
    #pragma unroll
    for (int i = 0; i < 4; i++) {
        sm[i] += __shfl_xor_sync(0xffffffffu, sm[i], 1);
        sm[i] += __shfl_xor_sync(0xffffffffu, sm[i], 2);
    }

    float acc2[2][4][4];
    #pragma unroll
    for (int mt = 0; mt < 2; mt++)
        #pragma unroll
        for (int nt = 0; nt < 4; nt++)
            #pragma unroll
            for (int r = 0; r < 4; r++) acc2[mt][nt][r] = 0.f;

    #pragma unroll
    for (int kc = 0; kc < 4; kc++) {
        unsigned ah[2][4];
        #pragma unroll
        for (int mt = 0; mt < 2; mt++) {
            ah[mt][0] = packh2(acc[mt][2*kc  ][0], acc[mt][2*kc  ][1]);
            ah[mt][1] = packh2(acc[mt][2*kc  ][2], acc[mt][2*kc  ][3]);
            ah[mt][2] = packh2(acc[mt][2*kc+1][0], acc[mt][2*kc+1][1]);
            ah[mt][3] = packh2(acc[mt][2*kc+1][2], acc[mt][2*kc+1][3]);
        }
        #pragma unroll
        for (int nt = 0; nt < 4; nt++) {
            unsigned b[2];
            int row = hoff + nt * 8 + (lane & 7);
            int col = kc * 16 + ((lane >> 3) & 1) * 8;
            ldsm2(b, smem_u32(&sv[row * AT_STR + col]));
            #pragma unroll
            for (int mt = 0; mt < 2; mt++) mma_f16(acc2[mt][nt], ah[mt], b);
        }
    }

    #pragma unroll
    for (int mt = 0; mt < 2; mt++)
        #pragma unroll
        for (int hf = 0; hf < 2; hf++) {
            float inv = 1.f / sm[mt * 2 + hf];
            int tok = mbase + mt * 16 + hf * 8 + (lane >> 2);
            __half* op = g_att + (size_t)(w * 64 + tok) * 256 + h * 32 + ((lane & 3) << 1);
            #pragma unroll
            for (int nt = 0; nt < 4; nt++) {
                unsigned hv = packh2(acc2[mt][nt][hf * 2] * inv, acc2[mt][nt][hf * 2 + 1] * inv);
                *(unsigned*)(op + nt * 8) = hv;
            }
        }
}

// ---------------- fp16 tensor-core NT GEMM (ldmatrix + swizzled smem) ----------------
// Block 128x128, 256 threads, 8 warps of 32x64. K-step 64 halves (128B rows, XOR-8 swizzle),
// 2-stage cp.async pipeline. EPI 0: +bias store fp16  1: +bias GELU fp16  2: scatter-add  3: add
template<int EPI, typename OutT>
__global__ __launch_bounds__(256, 2) void k_gemm(const __half* __restrict__ A,
                                                 const __half* __restrict__ B,
                                                 const float* __restrict__ bias,
                                                 OutT* __restrict__ Cout,
                                                 int N, int K, int shift) {
    extern __shared__ __half smem[];          // 2 stages * (A 128x64 + B 128x64)
    __half* As = smem;                        // stage s at + s*16384 halves? (A 8192 + B 8192)
    const int t = threadIdx.x;
    const int lane = t & 31, wid = t >> 5;
    const int warp_m = wid & 3, warp_n = wid >> 2;
    const int rowBase = blockIdx.y << 7;
    const int colBase = blockIdx.x << 7;
    const int mb = warp_m * 32, nb = warp_n * 64;

    float acc[2][8][4];
    #pragma unroll
    for (int mt = 0; mt < 2; mt++)
        #pragma unroll
        for (int nt = 0; nt < 8; nt++)
            #pragma unroll
            for (int r = 0; r < 4; r++) acc[mt][nt][r] = 0.f;

    // stage layout (halves): A at buf*16384, B at buf*16384 + 8192; row stride 64, swizzled 16B chunks
    auto load_tile = [&](int buf, int k0) {
        __half* sa = smem + buf * 16384;
        __half* sb = sa + 8192;
        #pragma unroll
        for (int j = 0; j < 4; j++) {
            int idx = t + j * 256;            // 1024 chunks of 16B
            int row = idx >> 3, ch = idx & 7;
            int sw = (ch ^ (row & 7)) << 3;
            cp16(&sa[row * 64 + sw], A + (size_t)(rowBase + row) * K + k0 + ch * 8);
        }
        #pragma unroll
        for (int j = 0; j < 4; j++) {
            int idx = t + j * 256;
            int row = idx >> 3, ch = idx & 7;
            int sw = (ch ^ (row & 7)) << 3;
            cp16(&sb[row * 64 + sw], B + (size_t)(colBase + row) * K + k0 + ch * 8);
        }
        asm volatile("cp.async.commit_group;\n" ::: "memory");
    };

    const int ntiles = K >> 6;
    load_tile(0, 0);
    for (int i = 0; i < ntiles; i++) {
        if (i + 1 < ntiles) {
            load_tile((i + 1) & 1, (i + 1) << 6);
            asm volatile("cp.async.wait_group 1;\n" ::: "memory");
        } else {
            asm volatile("cp.async.wait_group 0;\n" ::: "memory");
        }
        __syncthreads();
        const __half* sa = smem + (i & 1) * 16384;
        const __half* sb = sa + 8192;
        #pragma unroll
        for (int ks = 0; ks < 4; ks++) {
            unsigned af[2][4];
            #pragma unroll
            for (int mt = 0; mt < 2; mt++) {
                int tq = lane >> 3;
                int row = mb + mt * 16 + (tq & 1) * 8 + (lane & 7);
                int ch = ks * 2 + (tq >> 1);
                ldsm4(af[mt], smem_u32(&sa[row * 64 + ((ch ^ (row & 7)) << 3)]));
            }
            unsigned bf[8][2];
            #pragma unroll
            for (int np = 0; np < 4; np++) {
                int row = nb + np * 16 + ((lane >> 4) & 1) * 8 + (lane & 7);
                int ch = ks * 2 + ((lane >> 3) & 1);
                unsigned b4[4];
                ldsm4(b4, smem_u32(&sb[row * 64 + ((ch ^ (row & 7)) << 3)]));
                bf[np*2][0]   = b4[0]; bf[np*2][1]   = b4[1];
                bf[np*2+1][0] = b4[2]; bf[np*2+1][1] = b4[3];
            }
            #pragma unroll
            for (int mt = 0; mt < 2; mt++)
                #pragma unroll
                for (int nt = 0; nt < 8; nt++)
                    mma_f16(acc[mt][nt], af[mt], bf[nt]);
        }
        __syncthreads();
    }

    float2 bv[8];
    #pragma unroll
    for (int nt = 0; nt < 8; nt++)
        bv[nt] = *(const float2*)(bias + colBase + nb + nt * 8 + (lane & 3) * 2);

    #pragma unroll
    for (int mt = 0; mt < 2; mt++) {
        #pragma unroll
        for (int i = 0; i < 2; i++) {
            int row = rowBase + mb + mt * 16 + (lane >> 2) + i * 8;
            int dst = (EPI == 2) ? win_to_tok(row, shift) : row;
            #pragma unroll
            for (int nt = 0; nt < 8; nt++) {
                int col = colBase + nb + nt * 8 + (lane & 3) * 2;
                float v0 = acc[mt][nt][i * 2 + 0] + bv[nt].x;
                float v1 = acc[mt][nt][i * 2 + 1] + bv[nt].y;
                if (EPI == 0) {
                    *(unsigned*)((__half*)Cout + (size_t)row * N + col) = packh2(v0, v1);
                } else if (EPI == 1) {
                    v0 = 0.5f * v0 * (1.0f + erff(v0 * 0.70710678118654752f));
                    v1 = 0.5f * v1 * (1.0f + erff(v1 * 0.70710678118654752f));
                    *(unsigned*)((__half*)Cout + (size_t)row * N + col) = packh2(v0, v1);
                } else {
                    float2* rp = (float2*)(g_x + dst * 256 + col);
                    float2 r0 = *rp;
                    r0.x += v0; r0.y += v1;
                    *rp = r0;
                }
            }
        }
    }
}

// ---------------- final LN + [L,C] -> [C,L] transpose ----------------
__global__ __launch_bounds__(256) void k_final(const float* __restrict__ gam,
                                               const float* __restrict__ bet,
                                               float* __restrict__ out) {
    __shared__ float sm[256][33];
    int warp = threadIdx.x >> 5, lane = threadIdx.x & 31;
    int l0 = blockIdx.x << 5;
    float4 g0 = ((const float4*)gam)[lane*2], g1 = ((const float4*)gam)[lane*2+1];
    float4 b0 = ((const float4*)bet)[lane*2], b1 = ((const float4*)bet)[lane*2+1];
    #pragma unroll
    for (int i = 0; i < 4; i++) {
        int tok = (warp << 2) + i;
        const float4* xp = (const float4*)(g_x + (l0 + tok) * 256);
        float4 a = xp[lane*2], c = xp[lane*2+1];
        float s  = a.x + a.y + a.z + a.w + c.x + c.y + c.z + c.w;
        float sq = a.x*a.x + a.y*a.y + a.z*a.z + a.w*a.w
                 + c.x*c.x + c.y*c.y + c.z*c.z + c.w*c.w;
        #pragma unroll
        for (int o = 16; o; o >>= 1) {
            s  += __shfl_xor_sync(0xffffffffu, s, o);
            sq += __shfl_xor_sync(0xffffffffu, sq, o);
        }
        float mean = s * (1.0f / 256.0f);
        float inv = rsqrtf(sq * (1.0f / 256.0f) - mean * mean + 1e-5f);
        int cb = lane * 8;
        sm[cb+0][tok] = (a.x-mean)*inv*g0.x + b0.x;
        sm[cb+1][tok] = (a.y-mean)*inv*g0.y + b0.y;
        sm[cb+2][tok] = (a.z-mean)*inv*g0.z + b0.z;
        sm[cb+3][tok] = (a.w-mean)*inv*g0.w + b0.w;
        sm[cb+4][tok] = (c.x-mean)*inv*g1.x + b1.x;
        sm[cb+5][tok] = (c.y-mean)*inv*g1.y + b1.y;
        sm[cb+6][tok] = (c.z-mean)*inv*g1.z + b1.z;
        sm[cb+7][tok] = (c.w-mean)*inv*g1.w + b1.w;
    }
    __syncthreads();
    int lt = threadIdx.x & 31;
    int cw = threadIdx.x >> 5;
    #pragma unroll
    for (int cc = 0; cc < 32; cc++) {
        int c = (cc << 3) + cw;
        out[c * L_TOK + l0 + lt] = sm[c][lt];
    }
}

// ---------------- launch ----------------
#define GEMM_SMEM 65536
extern "C" void kernel_launch(void* const* d_in, const int* in_sizes, int n_in,
                              void* d_out, int out_size) {
    const float* x      = (const float*)d_in[0];
    const float* norm_g = (const float*)d_in[4];
    const float* norm_b = (const float*)d_in[5];
    float* out = (float*)d_out;

    __half *p_win, *p_qkv, *p_att, *p_mlp, *p_w;
    cudaGetSymbolAddress((void**)&p_win, g_win);
    cudaGetSymbolAddress((void**)&p_qkv, g_qkv);
    cudaGetSymbolAddress((void**)&p_att, g_att);
    cudaGetSymbolAddress((void**)&p_mlp, g_mlp);
    cudaGetSymbolAddress((void**)&p_w,   g_wbuf);

    cudaFuncSetAttribute(k_gemm<0, __half>, cudaFuncAttributeMaxDynamicSharedMemorySize, GEMM_SMEM);
    cudaFuncSetAttribute(k_gemm<1, __half>, cudaFuncAttributeMaxDynamicSharedMemorySize, GEMM_SMEM);
    cudaFuncSetAttribute(k_gemm<2, float >, cudaFuncAttributeMaxDynamicSharedMemorySize, GEMM_SMEM);
    cudaFuncSetAttribute(k_gemm<3, float >, cudaFuncAttributeMaxDynamicSharedMemorySize, GEMM_SMEM);

    k_copy<<<8192, 256>>>(x);
    k_roundall<<<1536, 256>>>((const float*)d_in[8],  (const float*)d_in[11],
                              (const float*)d_in[15], (const float*)d_in[17],
                              (const float*)d_in[21], (const float*)d_in[24],
                              (const float*)d_in[28], (const float*)d_in[30]);

    for (int blk = 0; blk < 2; blk++) {
        int o = 6 + blk * 13;
        int shift = blk ? 2 : 0;
        const float* n1g   = (const float*)d_in[o+0];
        const float* n1b   = (const float*)d_in[o+1];
        const float* qkvb  = (const float*)d_in[o+3];
        const float* rpb   = (const float*)d_in[o+4];
        const float* projb = (const float*)d_in[o+6];
        const float* n2g   = (const float*)d_in[o+7];
        const float* n2b   = (const float*)d_in[o+8];
        const float* fc1b  = (const float*)d_in[o+10];
        const float* fc2b  = (const float*)d_in[o+12];
        __half* wbase = p_w + blk * 786432;

        k_ln<1><<<4096, 256>>>(n1g, n1b, shift);
        k_gemm<0, __half><<<dim3(6, 256), 256, GEMM_SMEM>>>(p_win, wbase,          qkvb,  p_qkv, 768, 256, 0);
        k_attn_tc<<<2048, 128>>>(rpb, shift);
        k_gemm<2, float ><<<dim3(2, 256), 256, GEMM_SMEM>>>(p_att, wbase + 196608, projb, (float*)nullptr, 256, 256, shift);
        k_ln<0><<<4096, 256>>>(n2g, n2b, 0);
        k_gemm<1, __half><<<dim3(8, 256), 256, GEMM_SMEM>>>(p_win, wbase + 262144, fc1b,  p_mlp, 1024, 256, 0);
        k_gemm<3, float ><<<dim3(2, 256), 256, GEMM_SMEM>>>(p_mlp, wbase + 524288, fc2b,  (float*)nullptr, 256, 1024, 0);
    }

    k_final<<<1024, 256>>>(norm_g, norm_b, out);
}